// round 12
// baseline (speedup 1.0000x reference)
#include <cuda_runtime.h>
#include <cuda_bf16.h>
#include <math.h>

// Problem constants
#define Bn   8
#define Ln   4096
#define Cn   128
#define BL   32768            // B*L rows

typedef unsigned int u32;
typedef unsigned long long u64;
typedef __nv_bfloat16 bf16;

// ---------------- helpers ----------------
__device__ __forceinline__ u32 smem_u32(const void* p) {
    u32 a;
    asm("{ .reg .u64 t; cvta.to.shared.u64 t, %1; cvt.u32.u64 %0, t; }" : "=r"(a) : "l"(p));
    return a;
}
__device__ __forceinline__ void cp16(u32 dst, const void* src) {
    size_t g = __cvta_generic_to_global(src);
    asm volatile("cp.async.cg.shared.global [%0], [%1], 16;" :: "r"(dst), "l"(g));
}
__device__ __forceinline__ void ldm_x4(u32& r0, u32& r1, u32& r2, u32& r3, u32 addr) {
    asm volatile("ldmatrix.sync.aligned.m8n8.x4.shared.b16 {%0,%1,%2,%3}, [%4];"
                 : "=r"(r0), "=r"(r1), "=r"(r2), "=r"(r3) : "r"(addr));
}
__device__ __forceinline__ void ldmt_x4(u32& r0, u32& r1, u32& r2, u32& r3, u32 addr) {
    asm volatile("ldmatrix.sync.aligned.m8n8.x4.trans.shared.b16 {%0,%1,%2,%3}, [%4];"
                 : "=r"(r0), "=r"(r1), "=r"(r2), "=r"(r3) : "r"(addr));
}
__device__ __forceinline__ u32 bf2(float a, float b) {
    __nv_bfloat162 h;
    h.x = __float2bfloat16_rn(a);
    h.y = __float2bfloat16_rn(b);
    return *(u32*)&h;
}
__device__ __forceinline__ void mma_bf(float* c, const u32* a, u32 b0, u32 b1) {
    asm volatile(
        "mma.sync.aligned.m16n8k16.row.col.f32.bf16.bf16.f32 "
        "{%0,%1,%2,%3},{%4,%5,%6,%7},{%8,%9},{%0,%1,%2,%3};"
        : "+f"(c[0]), "+f"(c[1]), "+f"(c[2]), "+f"(c[3])
        : "r"(a[0]), "r"(a[1]), "r"(a[2]), "r"(a[3]), "r"(b0), "r"(b1));
}

// ---------------- scratch (device globals; no allocs allowed) ----------------
__device__ float d_x   [BL * Cn];      // running stream (fp32)
__device__ bf16  g_big16[BL * 512];    // concat input / qkv / MLP hidden (bf16)
__device__ bf16  g_xw16 [BL * Cn];     // LN output (bf16)
__device__ bf16  g_att16[BL * Cn];     // attention out (bf16)
__device__ bf16  g_loc16[BL * Cn];     // deform out (bf16, (B,C,L) flat)
__device__ bf16  g_x16  [BL * Cn];     // final g (bf16)
// transposed bf16 weights (N x K row-major)
__device__ bf16  g_redT[128 * 256];
__device__ bf16  g_qkvT[2 * 384 * 128];
__device__ bf16  g_pwT [2 * 128 * 128];
__device__ bf16  g_f1T [2 * 512 * 128];
__device__ bf16  g_f2T [2 * 128 * 512];
__device__ bf16  g_lfT [128 * 128];
__device__ bf16  g_gfT [128 * 128];
__device__ bf16  g_ffT [128 * 128];

// window-layout row m  ->  token index (b*L + ho*64 + wo)
__device__ __forceinline__ int win_to_token(int m, int shift) {
    int n    = m & 63;
    int bw   = m >> 6;
    int widx = bw & 63;
    int b    = bw >> 6;
    int wh = widx >> 3, ww = widx & 7;
    int r = n >> 3, s = n & 7;
    int ho = (wh * 8 + r + shift) & 63;
    int wo = (ww * 8 + s + shift) & 63;
    return (b << 12) + (ho << 6) + wo;
}
// token index -> window-layout row (exact inverse)
__device__ __forceinline__ int token_to_win(int t, int shift) {
    int b = t >> 12, rem = t & 4095;
    int ho = rem >> 6, wo = rem & 63;
    int u = (ho - shift) & 63, v = (wo - shift) & 63;
    int wh = u >> 3, r = u & 7;
    int ww = v >> 3, s = v & 7;
    return (((b << 6) + (wh << 3) + ww) << 6) + (r << 3) + s;
}

// ---------------- weight transpose-convert: (K x N fp32) -> (N x K bf16) ----------------
struct WEnt { const float* src; bf16* dst; int K; int N; };
struct WPack { WEnt e[12]; };

__global__ void __launch_bounds__(256) wconv_k(WPack p) {
    WEnt w = p.e[blockIdx.y];
    int total = w.K * w.N;
    for (int i = blockIdx.x * 256 + threadIdx.x; i < total; i += gridDim.x * 256) {
        int n = i / w.K, k = i - n * w.K;
        w.dst[i] = __float2bfloat16_rn(w.src[(size_t)k * w.N + n]);
    }
}

// ---------------- bf16 tensor-core GEMM: 64x128 tile, 8 warps (32x32/warp) ---------------
enum { M_PLAIN = 0, M_GELU, M_RES, M_PERMRES,
       M_PLAIN_LN, M_RES_LN, M_PERMRES_LN };

#define TSTRIDE 40            // 32 k halfs + 8 pad (80 B rows)
#define STG_HALFS 7680        // per stage: A 64x40 (2560) + B 128x40 (5120)
#define A_BYTES  (2560 * 2)
#define GEMM_SMEM (3 * STG_HALFS * 2)   // 46080 B, 3-stage ring
#define FUS_SMEM  (4 * STG_HALFS * 2)   // 61440 B, 4 resident k-tiles

template <int MODE>
__global__ void __launch_bounds__(256, 4) gemm_tc(
    const bf16* __restrict__ A, const bf16* __restrict__ BT,
    const float* __restrict__ bias, const float* __restrict__ extra,
    float* __restrict__ C, bf16* __restrict__ C16,
    const float* __restrict__ lng, const float* __restrict__ lnb,
    int N, int K, int shift)
{
    extern __shared__ bf16 smg[];
    int tid = threadIdx.x;
    int lane = tid & 31, warp = tid >> 5;       // warp 0..7
    int warp_m = warp & 1, warp_n = warp >> 1;  // 2 (M) x 4 (N), 32x32 tiles
    int m0 = blockIdx.y << 6, n0 = blockIdx.x << 7;
    int r = lane >> 2, c = lane & 3;

    const bool LN = (MODE == M_PLAIN_LN || MODE == M_RES_LN || MODE == M_PERMRES_LN);

    float acc[2][4][4];
#pragma unroll
    for (int i = 0; i < 2; i++)
#pragma unroll
        for (int j = 0; j < 4; j++)
#pragma unroll
            for (int q = 0; q < 4; q++) acc[i][j][q] = 0.f;

    const int prr = tid >> 2;                    // 0..63 (A) / 0..127 (B)
    const int pcc = (tid & 3) << 3;              // 0,8,16,24
    auto prefetch = [&](int k0, int s) {
        u32 abase = smem_u32(smg + s * STG_HALFS);
        u32 bbase = abase + A_BYTES;
        cp16(abase + (u32)(prr * TSTRIDE + pcc) * 2,
             A + (size_t)(m0 + prr) * K + k0 + pcc);
#pragma unroll
        for (int i = 0; i < 2; i++) {
            int ch = tid + (i << 8);
            int rr = ch >> 2, cc = (ch & 3) << 3;
            cp16(bbase + (u32)(rr * TSTRIDE + cc) * 2,
                 BT + (size_t)(n0 + rr) * K + k0 + cc);
        }
        asm volatile("cp.async.commit_group;");
    };

    int lrow = lane & 15;
    int lcol = (lane >> 4) << 3;                 // 0 or 8 halfs

    int ntk = K >> 5;
    prefetch(0, 0);
    int stage = 0;
    for (int t = 0; t < ntk; t++) {
        int ns = stage + 1; if (ns == 3) ns = 0;
        if (t + 1 < ntk) { prefetch((t + 1) << 5, ns);
                           asm volatile("cp.async.wait_group 1;"); }
        else             { asm volatile("cp.async.wait_group 0;"); }
        __syncthreads();

        u32 abase = smem_u32(smg + stage * STG_HALFS);
        u32 bbase = abase + A_BYTES;
#pragma unroll
        for (int ks = 0; ks < 2; ks++) {
            u32 af[2][4];
#pragma unroll
            for (int mt = 0; mt < 2; mt++)
                ldm_x4(af[mt][0], af[mt][1], af[mt][2], af[mt][3],
                       abase + (u32)((warp_m * 32 + mt * 16 + lrow) * TSTRIDE + ks * 16 + lcol) * 2);
            u32 bfr[2][4];
#pragma unroll
            for (int p = 0; p < 2; p++)
                ldm_x4(bfr[p][0], bfr[p][1], bfr[p][2], bfr[p][3],
                       bbase + (u32)((warp_n * 32 + p * 16 + lrow) * TSTRIDE + ks * 16 + lcol) * 2);
#pragma unroll
            for (int p = 0; p < 2; p++)
#pragma unroll
                for (int q = 0; q < 2; q++) {
                    int nt2 = p * 2 + q;
                    u32 b0 = bfr[p][q], b1 = bfr[p][q + 2];
#pragma unroll
                    for (int mt = 0; mt < 2; mt++)
                        mma_bf(acc[mt][nt2], af[mt], b0, b1);
                }
        }
        stage = ns;
    }

    if (!LN) {
#pragma unroll
        for (int mt = 0; mt < 2; mt++) {
            int row0 = m0 + warp_m * 32 + mt * 16 + r;
#pragma unroll
            for (int half = 0; half < 2; half++) {
                int row = row0 + half * 8;
                int dst = (MODE == M_PERMRES) ? win_to_token(row, shift) : row;
#pragma unroll
                for (int nt2 = 0; nt2 < 4; nt2++) {
                    int col = n0 + warp_n * 32 + nt2 * 8 + c * 2;
                    float v0 = acc[mt][nt2][half * 2 + 0] + bias[col];
                    float v1 = acc[mt][nt2][half * 2 + 1] + bias[col + 1];
                    size_t off = (size_t)dst * N + col;
                    if (MODE == M_GELU) {
                        v0 = 0.5f * v0 * (1.f + erff(v0 * 0.70710678118654752f));
                        v1 = 0.5f * v1 * (1.f + erff(v1 * 0.70710678118654752f));
                    } else if (MODE == M_RES || MODE == M_PERMRES) {
                        float2 e = *(const float2*)&extra[off];
                        v0 += e.x; v1 += e.y;
                    }
                    if (C)   *(float2*)&C[off] = make_float2(v0, v1);
                    if (C16) *(u32*)&C16[off]  = bf2(v0, v1);
                }
            }
        }
        return;
    }

    // ---- fused-LN epilogue (N == 128) ----
    float rsum[2][2], rsq[2][2];
#pragma unroll
    for (int mt = 0; mt < 2; mt++) {
        int row0 = m0 + warp_m * 32 + mt * 16 + r;
#pragma unroll
        for (int half = 0; half < 2; half++) {
            int row = row0 + half * 8;
            int dst = (MODE == M_PERMRES_LN) ? win_to_token(row, shift) : row;
            float s = 0.f, sq = 0.f;
#pragma unroll
            for (int nt2 = 0; nt2 < 4; nt2++) {
                int col = n0 + warp_n * 32 + nt2 * 8 + c * 2;
                float v0 = acc[mt][nt2][half * 2 + 0] + bias[col];
                float v1 = acc[mt][nt2][half * 2 + 1] + bias[col + 1];
                if (MODE == M_RES_LN || MODE == M_PERMRES_LN) {
                    float2 e = *(const float2*)&extra[(size_t)dst * 128 + col];
                    v0 += e.x; v1 += e.y;
                }
                acc[mt][nt2][half * 2 + 0] = v0;
                acc[mt][nt2][half * 2 + 1] = v1;
                s += v0 + v1; sq += v0 * v0 + v1 * v1;
            }
            s  += __shfl_xor_sync(0xffffffffu, s, 1);
            s  += __shfl_xor_sync(0xffffffffu, s, 2);
            sq += __shfl_xor_sync(0xffffffffu, sq, 1);
            sq += __shfl_xor_sync(0xffffffffu, sq, 2);
            rsum[mt][half] = s; rsq[mt][half] = sq;
        }
    }
    __syncthreads();
    float* part = (float*)smg;             // [64 rows][4 warp_n][2]
    if ((lane & 3) == 0) {
#pragma unroll
        for (int mt = 0; mt < 2; mt++)
#pragma unroll
            for (int half = 0; half < 2; half++) {
                int rowloc = warp_m * 32 + mt * 16 + (lane >> 2) + half * 8;
                part[rowloc * 8 + warp_n * 2 + 0] = rsum[mt][half];
                part[rowloc * 8 + warp_n * 2 + 1] = rsq[mt][half];
            }
    }
    __syncthreads();
#pragma unroll
    for (int mt = 0; mt < 2; mt++) {
#pragma unroll
        for (int half = 0; half < 2; half++) {
            int rowloc = warp_m * 32 + mt * 16 + r + half * 8;
            float s  = part[rowloc * 8] + part[rowloc * 8 + 2]
                     + part[rowloc * 8 + 4] + part[rowloc * 8 + 6];
            float sq = part[rowloc * 8 + 1] + part[rowloc * 8 + 3]
                     + part[rowloc * 8 + 5] + part[rowloc * 8 + 7];
            float mu = s * 0.0078125f;
            float var = sq * 0.0078125f - mu * mu;
            float rstd = rsqrtf(var + 1e-5f);
            int row = m0 + rowloc;
            int xdst, wdst;
            if (MODE == M_PERMRES_LN) { xdst = win_to_token(row, shift); wdst = xdst; }
            else                      { xdst = row; wdst = token_to_win(row, shift); }
#pragma unroll
            for (int nt2 = 0; nt2 < 4; nt2++) {
                int col = n0 + warp_n * 32 + nt2 * 8 + c * 2;
                float v0 = acc[mt][nt2][half * 2 + 0];
                float v1 = acc[mt][nt2][half * 2 + 1];
                *(float2*)&C[(size_t)xdst * 128 + col] = make_float2(v0, v1);
                float w0 = (v0 - mu) * rstd * lng[col]     + lnb[col];
                float w1 = (v1 - mu) * rstd * lng[col + 1] + lnb[col + 1];
                *(u32*)&C16[(size_t)wdst * 128 + col] = bf2(w0, w1);
            }
        }
    }
}

// ---------------- fused fusion + LSTM gate kernel (64-row tiles, 4 resident stages) -------
__device__ __forceinline__ void ml_k128(
    bf16* smg, const bf16* A, const bf16* BT, int m0,
    int tid, int warp_m, int warp_n, int lrow, int lcol,
    float (&acc)[2][4][4])
{
    __syncthreads();   // previous smem users done
    int prr = tid >> 2, pcc = (tid & 3) << 3;
#pragma unroll
    for (int s = 0; s < 4; s++) {
        u32 abase = smem_u32(smg + s * STG_HALFS);
        u32 bbase = abase + A_BYTES;
        cp16(abase + (u32)(prr * TSTRIDE + pcc) * 2,
             A + (size_t)(m0 + prr) * 128 + s * 32 + pcc);
#pragma unroll
        for (int i = 0; i < 2; i++) {
            int ch = tid + (i << 8);
            int rr = ch >> 2, cc = (ch & 3) << 3;
            cp16(bbase + (u32)(rr * TSTRIDE + cc) * 2,
                 BT + (size_t)rr * 128 + s * 32 + cc);
        }
    }
    asm volatile("cp.async.commit_group;");
    asm volatile("cp.async.wait_group 0;");
    __syncthreads();
#pragma unroll
    for (int t = 0; t < 4; t++) {
        u32 abase = smem_u32(smg + t * STG_HALFS);
        u32 bbase = abase + A_BYTES;
#pragma unroll
        for (int ks = 0; ks < 2; ks++) {
            u32 af[2][4];
#pragma unroll
            for (int mt = 0; mt < 2; mt++)
                ldm_x4(af[mt][0], af[mt][1], af[mt][2], af[mt][3],
                       abase + (u32)((warp_m * 32 + mt * 16 + lrow) * TSTRIDE + ks * 16 + lcol) * 2);
            u32 bfr[2][4];
#pragma unroll
            for (int p = 0; p < 2; p++)
                ldm_x4(bfr[p][0], bfr[p][1], bfr[p][2], bfr[p][3],
                       bbase + (u32)((warp_n * 32 + p * 16 + lrow) * TSTRIDE + ks * 16 + lcol) * 2);
#pragma unroll
            for (int p = 0; p < 2; p++)
#pragma unroll
                for (int q = 0; q < 2; q++) {
                    int nt2 = p * 2 + q;
#pragma unroll
                    for (int mt = 0; mt < 2; mt++)
                        mma_bf(acc[mt][nt2], af[mt], bfr[p][q], bfr[p][q + 2]);
                }
        }
    }
}

__global__ void __launch_bounds__(256, 3) fusion_k(
    const bf16* __restrict__ g16, const bf16* __restrict__ loc16,
    const bf16* __restrict__ gfT, const bf16* __restrict__ lfT,
    const bf16* __restrict__ ffT,
    const float* __restrict__ gf_b, const float* __restrict__ lf_b,
    const float* __restrict__ ff_b,
    const float* __restrict__ cx, float* __restrict__ outp)
{
    extern __shared__ bf16 smg[];
    int tid = threadIdx.x;
    int lane = tid & 31, warp = tid >> 5;
    int warp_m = warp & 1, warp_n = warp >> 1;
    int m0 = blockIdx.x << 6;
    int r = lane >> 2, c = lane & 3;
    int lrow = lane & 15;
    int lcol = (lane >> 4) << 3;

    float acc1[2][4][4], acc2[2][4][4];
#pragma unroll
    for (int i = 0; i < 2; i++)
#pragma unroll
        for (int j = 0; j < 4; j++)
#pragma unroll
            for (int q = 0; q < 4; q++) { acc1[i][j][q] = 0.f; acc2[i][j][q] = 0.f; }

    // ML1: g @ gfT ; ML2: loc @ lfT
    ml_k128(smg, g16, gfT, m0, tid, warp_m, warp_n, lrow, lcol, acc1);
    ml_k128(smg, loc16, lfT, m0, tid, warp_m, warp_n, lrow, lcol, acc2);

    __syncthreads();   // all ML2 smem reads done before t overwrites stages
    // t = relu((acc2+lf_b)*(acc1+gf_b)) -> stage A regions (k-tile = warp_n), ldmatrix layout
    {
        u32 abase = smem_u32(smg + warp_n * STG_HALFS);
#pragma unroll
        for (int mt = 0; mt < 2; mt++)
#pragma unroll
            for (int half = 0; half < 2; half++) {
                int row = warp_m * 32 + mt * 16 + r + half * 8;
#pragma unroll
                for (int nt2 = 0; nt2 < 4; nt2++) {
                    int cc = nt2 * 8 + c * 2;          // 0..31 within this k-tile
                    int col = warp_n * 32 + cc;
                    float a0 = acc1[mt][nt2][half * 2 + 0] + gf_b[col];
                    float a1 = acc1[mt][nt2][half * 2 + 1] + gf_b[col + 1];
                    float b0 = acc2[mt][nt2][half * 2 + 0] + lf_b[col];
                    float b1 = acc2[mt][nt2][half * 2 + 1] + lf_b[col + 1];
                    float t0 = a0 * b0, t1 = a1 * b1;
                    t0 = t0 > 0.f ? t0 : 0.f;
                    t1 = t1 > 0.f ? t1 : 0.f;
                    u32 pkv = bf2(t0, t1);
                    asm volatile("st.shared.b32 [%0], %1;"
                                 :: "r"(abase + (u32)(row * TSTRIDE + cc) * 2), "r"(pkv));
                }
            }
    }
    // prefetch ffT into stage B regions
    {
        int prr2 = tid >> 2, pcc2 = (tid & 3) << 3;
#pragma unroll
        for (int s = 0; s < 4; s++) {
            u32 bbase = smem_u32(smg + s * STG_HALFS) + A_BYTES;
#pragma unroll
            for (int i = 0; i < 2; i++) {
                int ch = tid + (i << 8);
                int rr = ch >> 2, cc = (ch & 3) << 3;
                cp16(bbase + (u32)(rr * TSTRIDE + cc) * 2,
                     ffT + (size_t)rr * 128 + s * 32 + cc);
            }
            (void)prr2; (void)pcc2;
        }
    }
    asm volatile("cp.async.commit_group;");
    asm volatile("cp.async.wait_group 0;");
    __syncthreads();

    // ML3: t @ ffT (both resident in smem)
#pragma unroll
    for (int i = 0; i < 2; i++)
#pragma unroll
        for (int j = 0; j < 4; j++)
#pragma unroll
            for (int q = 0; q < 4; q++) acc1[i][j][q] = 0.f;
#pragma unroll
    for (int t = 0; t < 4; t++) {
        u32 abase = smem_u32(smg + t * STG_HALFS);
        u32 bbase = abase + A_BYTES;
#pragma unroll
        for (int ks = 0; ks < 2; ks++) {
            u32 af[2][4];
#pragma unroll
            for (int mt = 0; mt < 2; mt++)
                ldm_x4(af[mt][0], af[mt][1], af[mt][2], af[mt][3],
                       abase + (u32)((warp_m * 32 + mt * 16 + lrow) * TSTRIDE + ks * 16 + lcol) * 2);
            u32 bfr[2][4];
#pragma unroll
            for (int p = 0; p < 2; p++)
                ldm_x4(bfr[p][0], bfr[p][1], bfr[p][2], bfr[p][3],
                       bbase + (u32)((warp_n * 32 + p * 16 + lrow) * TSTRIDE + ks * 16 + lcol) * 2);
#pragma unroll
            for (int p = 0; p < 2; p++)
#pragma unroll
                for (int q = 0; q < 2; q++) {
                    int nt2 = p * 2 + q;
#pragma unroll
                    for (int mt = 0; mt < 2; mt++)
                        mma_bf(acc1[mt][nt2], af[mt], bfr[p][q], bfr[p][q + 2]);
                }
        }
    }

    // gate epilogue -> d_out (fp32)
#pragma unroll
    for (int mt = 0; mt < 2; mt++) {
        int row0 = m0 + warp_m * 32 + mt * 16 + r;
#pragma unroll
        for (int half = 0; half < 2; half++) {
            int row = row0 + half * 8;
#pragma unroll
            for (int nt2 = 0; nt2 < 4; nt2++) {
                int col = warp_n * 32 + nt2 * 8 + c * 2;
                float v0 = acc1[mt][nt2][half * 2 + 0] + ff_b[col];
                float v1 = acc1[mt][nt2][half * 2 + 1] + ff_b[col + 1];
                size_t off = (size_t)row * 128 + col;
                float2 e = *(const float2*)&cx[off];
                float g0 = 1.f / (1.f + expf(-v0));
                float g1 = 1.f / (1.f + expf(-v1));
                float cy0 = g0 * (e.x + tanhf(v0));
                float cy1 = g1 * (e.y + tanhf(v1));
                *(float2*)&outp[off] = make_float2(g0 * tanhf(cy0), g1 * tanhf(cy1));
            }
        }
    }
}

// ---------------- concat + bf16 (reduce GEMM input) ----------------
__global__ void __launch_bounds__(256) concat_k(
    const float* __restrict__ xt, const float* __restrict__ hx, bf16* __restrict__ dst)
{
#pragma unroll
    for (int it = 0; it < 2; it++) {
        int g = (blockIdx.x * 256 + threadIdx.x) * 2 + it;
        int row = g >> 6, q = g & 63;
        const float* src = (q < 32) ? xt + (size_t)row * 128 + (q << 2)
                                    : hx + (size_t)row * 128 + ((q - 32) << 2);
        float4 v = *(const float4*)src;
        uint2 o = make_uint2(bf2(v.x, v.y), bf2(v.z, v.w));
        *(uint2*)(dst + (size_t)row * 256 + (q << 2)) = o;
    }
}

// ---------------- tensor-core window attention ----------------
#define ATT_STRIDE 136    // 128 d halfs + 8 pad (272 B rows)
#define ATT_SMEM   (3 * 64 * ATT_STRIDE * 2 + 900 * 4)

__global__ void __launch_bounds__(256) attn5(
    const bf16* __restrict__ qkv, const float* __restrict__ rp,
    bf16* __restrict__ out, int shift)
{
    extern __shared__ char smr[];
    bf16* qs = (bf16*)smr;
    bf16* ks = qs + 64 * ATT_STRIDE;
    bf16* vs = ks + 64 * ATT_STRIDE;
    float* rps = (float*)(vs + 64 * ATT_STRIDE);
    int tid = threadIdx.x;
    int lane = tid & 31, warp = tid >> 5;
    int bw = blockIdx.x;
    const float SCALE = 0.17677669529663687f;

    const bf16* base = qkv + (size_t)bw * 64 * 384;
#pragma unroll
    for (int i = 0; i < 12; i++) {
        int idx = tid + i * 256;
        int n = idx / 48, part = idx % 48;
        uint4 val = *(const uint4*)(base + (size_t)n * 384 + part * 8);
        bf16* dstp = (part < 16) ? qs : (part < 32) ? ks : vs;
        *(uint4*)&dstp[n * ATT_STRIDE + (part & 15) * 8] = val;
    }
    for (int i = tid; i < 900; i += 256) rps[i] = rp[i];
    __syncthreads();

    int h = warp >> 1;
    int m0 = (warp & 1) * 32;
    int cb = h * 32;
    int lrow = lane & 15;
    int lcol = (lane >> 4) << 3;

    u32 aq[2][2][4];
#pragma unroll
    for (int mt = 0; mt < 2; mt++)
#pragma unroll
        for (int kt = 0; kt < 2; kt++)
            ldm_x4(aq[mt][kt][0], aq[mt][kt][1], aq[mt][kt][2], aq[mt][kt][3],
                   smem_u32(&qs[(m0 + 16 * mt + lrow) * ATT_STRIDE + cb + 16 * kt + lcol]));

    float sacc[2][8][4];
#pragma unroll
    for (int mt = 0; mt < 2; mt++)
#pragma unroll
        for (int nt = 0; nt < 8; nt++)
#pragma unroll
            for (int q = 0; q < 4; q++) sacc[mt][nt][q] = 0.f;

#pragma unroll
    for (int ntp = 0; ntp < 4; ntp++)
#pragma unroll
        for (int kt = 0; kt < 2; kt++) {
            u32 b0, b1, b2, b3;
            ldm_x4(b0, b1, b2, b3,
                   smem_u32(&ks[(16 * ntp + lrow) * ATT_STRIDE + cb + 16 * kt + lcol]));
#pragma unroll
            for (int mt = 0; mt < 2; mt++) {
                mma_bf(sacc[mt][2 * ntp],     aq[mt][kt], b0, b2);
                mma_bf(sacc[mt][2 * ntp + 1], aq[mt][kt], b1, b3);
            }
        }

    int widx = bw & 63;
    int wh = widx >> 3, ww = widx & 7;
#pragma unroll
    for (int mt = 0; mt < 2; mt++)
#pragma unroll
        for (int q = 0; q < 4; q++) {
            int t1 = m0 + 16 * mt + (lane >> 2) + ((q >> 1) << 3);
            int r1 = t1 >> 3, s1 = t1 & 7;
            int h1 = wh * 8 + r1, w1 = ww * 8 + s1;
            int img1 = (h1 < 56 ? 0 : (h1 < 60 ? 1 : 2)) * 3 + (w1 < 56 ? 0 : (w1 < 60 ? 1 : 2));
#pragma unroll
            for (int nt = 0; nt < 8; nt++) {
                int t2 = nt * 8 + 2 * (lane & 3) + (q & 1);
                int r2 = t2 >> 3, s2 = t2 & 7;
                float v = sacc[mt][nt][q] * SCALE
                        + rps[((r1 - r2 + 7) * 15 + (s1 - s2 + 7)) * 4 + h];
                if (shift) {
                    int h2 = wh * 8 + r2, w2 = ww * 8 + s2;
                    int img2 = (h2 < 56 ? 0 : (h2 < 60 ? 1 : 2)) * 3 + (w2 < 56 ? 0 : (w2 < 60 ? 1 : 2));
                    if (img1 != img2) v -= 100.f;
                }
                sacc[mt][nt][q] = v;
            }
        }

#pragma unroll
    for (int mt = 0; mt < 2; mt++)
#pragma unroll
        for (int half = 0; half < 2; half++) {
            float mx = -1e30f;
#pragma unroll
            for (int nt = 0; nt < 8; nt++) {
                mx = fmaxf(mx, sacc[mt][nt][2 * half]);
                mx = fmaxf(mx, sacc[mt][nt][2 * half + 1]);
            }
            mx = fmaxf(mx, __shfl_xor_sync(0xffffffffu, mx, 1));
            mx = fmaxf(mx, __shfl_xor_sync(0xffffffffu, mx, 2));
            float sum = 0.f;
#pragma unroll
            for (int nt = 0; nt < 8; nt++) {
#pragma unroll
                for (int qq = 0; qq < 2; qq++) {
                    float e = __expf(sacc[mt][nt][2 * half + qq] - mx);
                    sacc[mt][nt][2 * half + qq] = e;
                    sum += e;
                }
            }
            sum += __shfl_xor_sync(0xffffffffu, sum, 1);
            sum += __shfl_xor_sync(0xffffffffu, sum, 2);
            float inv = 1.f / sum;
#pragma unroll
            for (int nt = 0; nt < 8; nt++) {
                sacc[mt][nt][2 * half] *= inv;
                sacc[mt][nt][2 * half + 1] *= inv;
            }
        }

    u32 pa[2][4][4];
#pragma unroll
    for (int mt = 0; mt < 2; mt++)
#pragma unroll
        for (int j = 0; j < 4; j++) {
            pa[mt][j][0] = bf2(sacc[mt][2 * j][0],     sacc[mt][2 * j][1]);
            pa[mt][j][1] = bf2(sacc[mt][2 * j][2],     sacc[mt][2 * j][3]);
            pa[mt][j][2] = bf2(sacc[mt][2 * j + 1][0], sacc[mt][2 * j + 1][1]);
            pa[mt][j][3] = bf2(sacc[mt][2 * j + 1][2], sacc[mt][2 * j + 1][3]);
        }

    float oacc[2][4][4];
#pragma unroll
    for (int mt = 0; mt < 2; mt++)
#pragma unroll
        for (int nt2 = 0; nt2 < 4; nt2++)
#pragma unroll
            for (int q = 0; q < 4; q++) oacc[mt][nt2][q] = 0.f;

#pragma unroll
    for (int j = 0; j < 4; j++)
#pragma unroll
        for (int ntp = 0; ntp < 2; ntp++) {
            u32 b0, b1, b2, b3;
            ldmt_x4(b0, b1, b2, b3,
                    smem_u32(&vs[(16 * j + lrow) * ATT_STRIDE + cb + 16 * ntp + lcol]));
#pragma unroll
            for (int mt = 0; mt < 2; mt++) {
                mma_bf(oacc[mt][2 * ntp],     pa[mt][j], b0, b1);
                mma_bf(oacc[mt][2 * ntp + 1], pa[mt][j], b2, b3);
            }
        }

#pragma unroll
    for (int mt = 0; mt < 2; mt++) {
        int row0 = bw * 64 + m0 + 16 * mt + (lane >> 2);
        int col  = cb + 2 * (lane & 3);
#pragma unroll
        for (int nt2 = 0; nt2 < 4; nt2++) {
            *(u32*)&out[(size_t)row0 * 128 + col + nt2 * 8]       = bf2(oacc[mt][nt2][0], oacc[mt][nt2][1]);
            *(u32*)&out[(size_t)(row0 + 8) * 128 + col + nt2 * 8] = bf2(oacc[mt][nt2][2], oacc[mt][nt2][3]);
        }
    }
}

// ---------------- fused deformable-conv branch (offset/mask conv + gather) ----------------
__global__ void __launch_bounds__(256) local_k(
    const float* __restrict__ xt,
    const float* __restrict__ ow, const float* __restrict__ ob,
    const float* __restrict__ mw, const float* __restrict__ mb,
    bf16* __restrict__ outp)
{
    __shared__ float rows[34][128];
    __shared__ float wo_s[1152], wm_s[1152];
    __shared__ int   s_fp[3][32];
    __shared__ float s_a0[3][32], s_a1[3][32];
    __shared__ bf16  smout[32][130];
    int b  = blockIdx.x >> 7;
    int l0 = (blockIdx.x & 127) << 5;
    int tid = threadIdx.x;
    int warp = tid >> 5, lane = tid & 31;

    for (int i = tid; i < 1152; i += 256) { wo_s[i] = ow[i]; wm_s[i] = mw[i]; }
#pragma unroll
    for (int i = 0; i < 5; i++) {
        int idx = i * 256 + tid;             // float4 ids, need 34*32 = 1088
        if (idx < 1088) {
            int rr = idx >> 5, c4 = (idx & 31) << 2;
            int l = l0 - 1 + rr;
            if (l >= 0 && l < 4096)
                *(float4*)&rows[rr][c4] = *(const float4*)(xt + ((size_t)b * 4096 + l) * 128 + c4);
        }
    }
    __syncthreads();

    int c0 = lane << 2;
#pragma unroll
    for (int it = 0; it < 4; it++) {
        int tl = warp * 4 + it;              // local token 0..31
        int l = l0 + tl;
        float so[3] = {0.f, 0.f, 0.f}, sm[3] = {0.f, 0.f, 0.f};
#pragma unroll
        for (int j = 0; j < 3; j++) {
            int ll = l + j - 1;
            if (ll < 0 || ll > 4095) continue;
            float4 xv = *(const float4*)&rows[tl + j][c0];
#pragma unroll
            for (int k = 0; k < 3; k++) {
                const float* owp = wo_s + k * 384 + j;
                const float* mwp = wm_s + k * 384 + j;
                so[k] += xv.x * owp[(c0 + 0) * 3] + xv.y * owp[(c0 + 1) * 3]
                       + xv.z * owp[(c0 + 2) * 3] + xv.w * owp[(c0 + 3) * 3];
                sm[k] += xv.x * mwp[(c0 + 0) * 3] + xv.y * mwp[(c0 + 1) * 3]
                       + xv.z * mwp[(c0 + 2) * 3] + xv.w * mwp[(c0 + 3) * 3];
            }
        }
#pragma unroll
        for (int o = 16; o > 0; o >>= 1) {
#pragma unroll
            for (int k = 0; k < 3; k++) {
                so[k] += __shfl_xor_sync(0xffffffffu, so[k], o);
                sm[k] += __shfl_xor_sync(0xffffffffu, sm[k], o);
            }
        }
        if (lane < 3) {
            int k = lane;
            float off = ob[k] + so[k];
            float mk  = mb[k] + sm[k];
            float mask = 1.f / (1.f + expf(-mk));
            float pos = fminf(fmaxf((float)l + off, 0.f), 4095.f);
            float fpf = floorf(pos);
            int f = (int)fpf;
            float alpha = pos - fpf;
            s_fp[k][tl] = f;
            s_a0[k][tl] = (1.f - alpha) * mask;
            s_a1[k][tl] = alpha * mask;
        }
    }
    __syncthreads();

    // phase 2: gather + bf16, transpose via smem, coalesced (B,C,L) write
#pragma unroll
    for (int i = 0; i < 16; i++) {
        int idx = i * 256 + tid;          // 0..4095
        int dl = idx >> 7, c = idx & 127;
        float o = 0.f;
#pragma unroll
        for (int k = 0; k < 3; k++) {
            int f  = s_fp[k][dl];
            int cp = min(f + 1, 4095);
            o += xt[((size_t)b * 4096 + f)  * 128 + c] * s_a0[k][dl]
               + xt[((size_t)b * 4096 + cp) * 128 + c] * s_a1[k][dl];
        }
        smout[dl][c] = __float2bfloat16_rn(o);
    }
    __syncthreads();
#pragma unroll
    for (int i = 0; i < 16; i++) {
        int idx = i * 256 + tid;
        int c = idx >> 5, dl = idx & 31;
        outp[(size_t)b * 524288 + (size_t)c * 4096 + l0 + dl] = smout[dl][c];
    }
}

// ---------------- host launcher ----------------
extern "C" void kernel_launch(void* const* d_in, const int* in_sizes, int n_in,
                              void* d_out, int out_size)
{
    const float* xt    = (const float*)d_in[0];
    const float* hx    = (const float*)d_in[1];
    const float* cx    = (const float*)d_in[2];
    const float* red_w = (const float*)d_in[3];
    const float* red_b = (const float*)d_in[4];
    const float* n1g   = (const float*)d_in[5];
    const float* n1b   = (const float*)d_in[6];
    const float* qkvw  = (const float*)d_in[7];
    const float* qkvb  = (const float*)d_in[8];
    const float* rp    = (const float*)d_in[9];
    const float* pw    = (const float*)d_in[10];
    const float* pb    = (const float*)d_in[11];
    const float* n2g   = (const float*)d_in[12];
    const float* n2b   = (const float*)d_in[13];
    const float* f1w   = (const float*)d_in[14];
    const float* f1b   = (const float*)d_in[15];
    const float* f2w   = (const float*)d_in[16];
    const float* f2b   = (const float*)d_in[17];
    const float* off_w = (const float*)d_in[18];
    const float* off_b = (const float*)d_in[19];
    const float* msk_w = (const float*)d_in[20];
    const float* msk_b = (const float*)d_in[21];
    const float* lf_w  = (const float*)d_in[22];
    const float* lf_b  = (const float*)d_in[23];
    const float* gf_w  = (const float*)d_in[24];
    const float* gf_b  = (const float*)d_in[25];
    const float* ff_w  = (const float*)d_in[26];
    const float* ff_b  = (const float*)d_in[27];

    float* px;
    bf16 *pbig16, *pxw16, *patt16, *ploc16, *px16;
    bf16 *predT, *pqkvT, *ppwT, *pf1T, *pf2T, *plfT, *pgfT, *pffT;
    cudaGetSymbolAddress((void**)&px,    d_x);
    cudaGetSymbolAddress((void**)&pbig16, g_big16);
    cudaGetSymbolAddress((void**)&pxw16, g_xw16);
    cudaGetSymbolAddress((void**)&patt16, g_att16);
    cudaGetSymbolAddress((void**)&ploc16, g_loc16);
    cudaGetSymbolAddress((void**)&px16,  g_x16);
    cudaGetSymbolAddress((void**)&predT, g_redT);
    cudaGetSymbolAddress((void**)&pqkvT, g_qkvT);
    cudaGetSymbolAddress((void**)&ppwT,  g_pwT);
    cudaGetSymbolAddress((void**)&pf1T,  g_f1T);
    cudaGetSymbolAddress((void**)&pf2T,  g_f2T);
    cudaGetSymbolAddress((void**)&plfT,  g_lfT);
    cudaGetSymbolAddress((void**)&pgfT,  g_gfT);
    cudaGetSymbolAddress((void**)&pffT,  g_ffT);

    cudaFuncSetAttribute(gemm_tc<M_PLAIN>,      cudaFuncAttributeMaxDynamicSharedMemorySize, GEMM_SMEM);
    cudaFuncSetAttribute(gemm_tc<M_GELU>,       cudaFuncAttributeMaxDynamicSharedMemorySize, GEMM_SMEM);
    cudaFuncSetAttribute(gemm_tc<M_RES>,        cudaFuncAttributeMaxDynamicSharedMemorySize, GEMM_SMEM);
    cudaFuncSetAttribute(gemm_tc<M_PLAIN_LN>,   cudaFuncAttributeMaxDynamicSharedMemorySize, GEMM_SMEM);
    cudaFuncSetAttribute(gemm_tc<M_RES_LN>,     cudaFuncAttributeMaxDynamicSharedMemorySize, GEMM_SMEM);
    cudaFuncSetAttribute(gemm_tc<M_PERMRES_LN>, cudaFuncAttributeMaxDynamicSharedMemorySize, GEMM_SMEM);
    cudaFuncSetAttribute(fusion_k,              cudaFuncAttributeMaxDynamicSharedMemorySize, FUS_SMEM);
    cudaFuncSetAttribute(attn5,                 cudaFuncAttributeMaxDynamicSharedMemorySize, ATT_SMEM);

    // weight transpose-convert (fp32 KxN -> bf16 NxK)
    WPack wp;
    wp.e[0]  = { red_w,           predT,           256, 128 };
    wp.e[1]  = { qkvw,            pqkvT,           128, 384 };
    wp.e[2]  = { qkvw + 49152,    pqkvT + 49152,   128, 384 };
    wp.e[3]  = { pw,              ppwT,            128, 128 };
    wp.e[4]  = { pw + 16384,      ppwT + 16384,    128, 128 };
    wp.e[5]  = { f1w,             pf1T,            128, 512 };
    wp.e[6]  = { f1w + 65536,     pf1T + 65536,    128, 512 };
    wp.e[7]  = { f2w,             pf2T,            512, 128 };
    wp.e[8]  = { f2w + 65536,     pf2T + 65536,    512, 128 };
    wp.e[9]  = { lf_w,            plfT,            128, 128 };
    wp.e[10] = { gf_w,            pgfT,            128, 128 };
    wp.e[11] = { ff_w,            pffT,            128, 128 };
    wconv_k<<<dim3(48, 12), 256>>>(wp);

    // local (deformable) branch — fused offsets + gather
    local_k<<<Bn * 128, 256>>>(xt, off_w, off_b, msk_w, msk_b, ploc16);

    // global branch: concat then reduce GEMM (K=256) + fused LN1(block0, shift 0)
    concat_k<<<BL * 64 / 512, 256>>>(xt, hx, pbig16);
    gemm_tc<M_PLAIN_LN><<<dim3(1, 512), 256, GEMM_SMEM>>>(
        pbig16, predT, red_b, nullptr, px, pxw16, n1g, n1b, 128, 256, 0);

    for (int i = 0; i < 2; i++) {
        int shift = i ? 4 : 0;
        gemm_tc<M_PLAIN><<<dim3(3, 512), 256, GEMM_SMEM>>>(
            pxw16, pqkvT + i * 49152, qkvb + i * 384, nullptr,
            nullptr, pbig16, nullptr, nullptr, 384, 128, 0);
        attn5<<<512, 256, ATT_SMEM>>>(pbig16, rp + i * 900, patt16, shift);
        gemm_tc<M_PERMRES_LN><<<dim3(1, 512), 256, GEMM_SMEM>>>(
            patt16, ppwT + i * 16384, pb + i * 128, px,
            px, pxw16, n2g + i * 128, n2b + i * 128, 128, 128, shift);
        gemm_tc<M_GELU><<<dim3(4, 512), 256, GEMM_SMEM>>>(
            pxw16, pf1T + i * 65536, f1b + i * 512, nullptr,
            nullptr, pbig16, nullptr, nullptr, 512, 128, 0);
        if (i == 0) {
            gemm_tc<M_RES_LN><<<dim3(1, 512), 256, GEMM_SMEM>>>(
                pbig16, pf2T, f2b, px,
                px, pxw16, n1g + 128, n1b + 128, 128, 512, 4);
        } else {
            gemm_tc<M_RES><<<dim3(1, 512), 256, GEMM_SMEM>>>(
                pbig16, pf2T + 65536, f2b + 128, px,
                px, px16, nullptr, nullptr, 128, 512, 0);
        }
    }

    // fused fusion + LSTM gate
    fusion_k<<<512, 256, FUS_SMEM>>>(px16, ploc16, pgfT, plfT, pffT,
                                     gf_b, lf_b, ff_b, cx, (float*)d_out);
}

// round 13
// speedup vs baseline: 1.5008x; 1.5008x over previous
#include <cuda_runtime.h>
#include <cuda_bf16.h>
#include <math.h>

// Problem constants
#define Bn   8
#define Ln   4096
#define Cn   128
#define BL   32768            // B*L rows

typedef unsigned int u32;
typedef unsigned long long u64;
typedef __nv_bfloat16 bf16;

// ---------------- helpers ----------------
__device__ __forceinline__ u32 smem_u32(const void* p) {
    u32 a;
    asm("{ .reg .u64 t; cvta.to.shared.u64 t, %1; cvt.u32.u64 %0, t; }" : "=r"(a) : "l"(p));
    return a;
}
__device__ __forceinline__ void cp16(u32 dst, const void* src) {
    size_t g = __cvta_generic_to_global(src);
    asm volatile("cp.async.cg.shared.global [%0], [%1], 16;" :: "r"(dst), "l"(g));
}
__device__ __forceinline__ void ldm_x4(u32& r0, u32& r1, u32& r2, u32& r3, u32 addr) {
    asm volatile("ldmatrix.sync.aligned.m8n8.x4.shared.b16 {%0,%1,%2,%3}, [%4];"
                 : "=r"(r0), "=r"(r1), "=r"(r2), "=r"(r3) : "r"(addr));
}
__device__ __forceinline__ void ldmt_x4(u32& r0, u32& r1, u32& r2, u32& r3, u32 addr) {
    asm volatile("ldmatrix.sync.aligned.m8n8.x4.trans.shared.b16 {%0,%1,%2,%3}, [%4];"
                 : "=r"(r0), "=r"(r1), "=r"(r2), "=r"(r3) : "r"(addr));
}
__device__ __forceinline__ u32 bf2(float a, float b) {
    __nv_bfloat162 h;
    h.x = __float2bfloat16_rn(a);
    h.y = __float2bfloat16_rn(b);
    return *(u32*)&h;
}
__device__ __forceinline__ void mma_bf(float* c, const u32* a, u32 b0, u32 b1) {
    asm volatile(
        "mma.sync.aligned.m16n8k16.row.col.f32.bf16.bf16.f32 "
        "{%0,%1,%2,%3},{%4,%5,%6,%7},{%8,%9},{%0,%1,%2,%3};"
        : "+f"(c[0]), "+f"(c[1]), "+f"(c[2]), "+f"(c[3])
        : "r"(a[0]), "r"(a[1]), "r"(a[2]), "r"(a[3]), "r"(b0), "r"(b1));
}

// ---------------- scratch (device globals; no allocs allowed) ----------------
__device__ float d_x   [BL * Cn];      // running stream (fp32)
__device__ bf16  g_big16[BL * 512];    // qkv / MLP hidden (bf16)
__device__ bf16  g_xw16 [BL * Cn];     // LN output (bf16)
__device__ bf16  g_att16[BL * Cn];     // attention out (bf16)
__device__ bf16  g_loc16[BL * Cn];     // deform out (bf16, (B,C,L) flat)
__device__ bf16  g_x16  [BL * Cn];     // final g (bf16)
// transposed bf16 weights (N x K row-major)
__device__ bf16  g_redT[128 * 256];
__device__ bf16  g_qkvT[2 * 384 * 128];
__device__ bf16  g_pwT [2 * 128 * 128];
__device__ bf16  g_f1T [2 * 512 * 128];
__device__ bf16  g_f2T [2 * 128 * 512];
__device__ bf16  g_lfT [128 * 128];
__device__ bf16  g_gfT [128 * 128];
__device__ bf16  g_ffT [128 * 128];

// window-layout row m  ->  token index (b*L + ho*64 + wo)
__device__ __forceinline__ int win_to_token(int m, int shift) {
    int n    = m & 63;
    int bw   = m >> 6;
    int widx = bw & 63;
    int b    = bw >> 6;
    int wh = widx >> 3, ww = widx & 7;
    int r = n >> 3, s = n & 7;
    int ho = (wh * 8 + r + shift) & 63;
    int wo = (ww * 8 + s + shift) & 63;
    return (b << 12) + (ho << 6) + wo;
}
// token index -> window-layout row (exact inverse)
__device__ __forceinline__ int token_to_win(int t, int shift) {
    int b = t >> 12, rem = t & 4095;
    int ho = rem >> 6, wo = rem & 63;
    int u = (ho - shift) & 63, v = (wo - shift) & 63;
    int wh = u >> 3, r = u & 7;
    int ww = v >> 3, s = v & 7;
    return (((b << 6) + (wh << 3) + ww) << 6) + (r << 3) + s;
}

// ---------------- weight transpose-convert: (K x N fp32) -> (N x K bf16) ----------------
struct WEnt { const float* src; bf16* dst; int K; int N; };
struct WPack { WEnt e[12]; };

__global__ void __launch_bounds__(256) wconv_k(WPack p) {
    WEnt w = p.e[blockIdx.y];
    int total = w.K * w.N;
    for (int i = blockIdx.x * 256 + threadIdx.x; i < total; i += gridDim.x * 256) {
        int n = i / w.K, k = i - n * w.K;
        w.dst[i] = __float2bfloat16_rn(w.src[(size_t)k * w.N + n]);
    }
}

// ---------------- bf16 tensor-core GEMM: 128x128 tile, 16 warps (32x32/warp) ---------------
enum { M_PLAIN = 0, M_GELU, M_RES, M_PERMRES,
       M_PLAIN_LN, M_RES_LN, M_PERMRES_LN, M_CONCAT_LN };

#define TSTRIDE 40            // 32 k halfs + 8 pad (80 B rows)
#define STG_HALFS 10240       // per stage: A 5120 halfs + B 5120 halfs (20480 B)
#define GEMM_SMEM (4 * STG_HALFS * 2)   // 81920 B

template <int MODE>
__global__ void __launch_bounds__(512, 2) gemm_tc(
    const bf16* __restrict__ A, const bf16* __restrict__ BT,
    const float* __restrict__ bias, const float* __restrict__ extra,
    float* __restrict__ C, bf16* __restrict__ C16,
    const float* __restrict__ lng, const float* __restrict__ lnb,
    int N, int K, int shift,
    const float* __restrict__ Ax, const float* __restrict__ Ah)
{
    extern __shared__ bf16 smg[];
    int tid = threadIdx.x;
    int lane = tid & 31, warp = tid >> 5;       // warp 0..15
    int warp_m = warp & 3, warp_n = warp >> 2;  // 4 (M) x 4 (N), 32x32 tiles
    int m0 = blockIdx.y << 7, n0 = blockIdx.x << 7;
    int r = lane >> 2, c = lane & 3;

    const bool LN = (MODE == M_PLAIN_LN || MODE == M_RES_LN ||
                     MODE == M_PERMRES_LN || MODE == M_CONCAT_LN);

    float acc[2][4][4];
#pragma unroll
    for (int i = 0; i < 2; i++)
#pragma unroll
        for (int j = 0; j < 4; j++)
#pragma unroll
            for (int q = 0; q < 4; q++) acc[i][j][q] = 0.f;

    const int prr = tid >> 2;                    // 0..127
    const int pcc = (tid & 3) << 3;              // 0,8,16,24
    auto prefetch = [&](int k0, int s) {
        u32 abase = smem_u32(smg + s * STG_HALFS);
        u32 bbase = abase + 5120 * 2;
        if (MODE == M_CONCAT_LN) {
            // fused concat(xt,hx) -> bf16 staging (fp32 LDG + cvt + STS)
            int gk = k0 + pcc;
            const float* srcp = (gk < 128) ? Ax + (size_t)(m0 + prr) * 128 + gk
                                           : Ah + (size_t)(m0 + prr) * 128 + gk - 128;
            float4 v0 = *(const float4*)srcp;
            float4 v1 = *(const float4*)(srcp + 4);
            u32 w0 = bf2(v0.x, v0.y), w1 = bf2(v0.z, v0.w);
            u32 w2 = bf2(v1.x, v1.y), w3 = bf2(v1.z, v1.w);
            asm volatile("st.shared.v4.b32 [%0], {%1,%2,%3,%4};"
                         :: "r"(abase + (u32)(prr * TSTRIDE + pcc) * 2),
                            "r"(w0), "r"(w1), "r"(w2), "r"(w3));
        } else {
            cp16(abase + (u32)(prr * TSTRIDE + pcc) * 2,
                 A + (size_t)(m0 + prr) * K + k0 + pcc);
        }
        cp16(bbase + (u32)(prr * TSTRIDE + pcc) * 2,
             BT + (size_t)(n0 + prr) * K + k0 + pcc);
        asm volatile("cp.async.commit_group;");
    };

    int lrow = lane & 15;
    int lcol = (lane >> 4) << 3;                 // 0 or 8 halfs

    int ntk = K >> 5;
    prefetch(0, 0);
    if (ntk > 1) prefetch(32, 1);
    for (int t = 0; t < ntk; t++) {
        if (t + 2 < ntk) prefetch((t + 2) << 5, (t + 2) & 3);
        if (t < ntk - 2)       asm volatile("cp.async.wait_group 2;");
        else if (t == ntk - 2) asm volatile("cp.async.wait_group 1;");
        else                   asm volatile("cp.async.wait_group 0;");
        __syncthreads();

        u32 abase = smem_u32(smg + (t & 3) * STG_HALFS);
        u32 bbase = abase + 5120 * 2;
#pragma unroll
        for (int ks = 0; ks < 2; ks++) {
            u32 af[2][4];
#pragma unroll
            for (int mt = 0; mt < 2; mt++)
                ldm_x4(af[mt][0], af[mt][1], af[mt][2], af[mt][3],
                       abase + (u32)((warp_m * 32 + mt * 16 + lrow) * TSTRIDE + ks * 16 + lcol) * 2);
            u32 bfr[2][4];
#pragma unroll
            for (int p = 0; p < 2; p++)
                ldm_x4(bfr[p][0], bfr[p][1], bfr[p][2], bfr[p][3],
                       bbase + (u32)((warp_n * 32 + p * 16 + lrow) * TSTRIDE + ks * 16 + lcol) * 2);
#pragma unroll
            for (int p = 0; p < 2; p++)
#pragma unroll
                for (int q = 0; q < 2; q++) {
                    int nt2 = p * 2 + q;
                    u32 b0 = bfr[p][q], b1 = bfr[p][q + 2];
#pragma unroll
                    for (int mt = 0; mt < 2; mt++)
                        mma_bf(acc[mt][nt2], af[mt], b0, b1);
                }
        }
    }

    if (!LN) {
#pragma unroll
        for (int mt = 0; mt < 2; mt++) {
            int row0 = m0 + warp_m * 32 + mt * 16 + r;
#pragma unroll
            for (int half = 0; half < 2; half++) {
                int row = row0 + half * 8;
                int dst = (MODE == M_PERMRES) ? win_to_token(row, shift) : row;
#pragma unroll
                for (int nt2 = 0; nt2 < 4; nt2++) {
                    int col = n0 + warp_n * 32 + nt2 * 8 + c * 2;
                    float v0 = acc[mt][nt2][half * 2 + 0] + bias[col];
                    float v1 = acc[mt][nt2][half * 2 + 1] + bias[col + 1];
                    size_t off = (size_t)dst * N + col;
                    if (MODE == M_GELU) {
                        v0 = 0.5f * v0 * (1.f + erff(v0 * 0.70710678118654752f));
                        v1 = 0.5f * v1 * (1.f + erff(v1 * 0.70710678118654752f));
                    } else if (MODE == M_RES || MODE == M_PERMRES) {
                        float2 e = *(const float2*)&extra[off];
                        v0 += e.x; v1 += e.y;
                    }
                    if (C)   *(float2*)&C[off] = make_float2(v0, v1);
                    if (C16) *(u32*)&C16[off]  = bf2(v0, v1);
                }
            }
        }
        return;
    }

    // ---- fused-LN epilogue (N == 128) ----
    float rsum[2][2], rsq[2][2];
#pragma unroll
    for (int mt = 0; mt < 2; mt++) {
        int row0 = m0 + warp_m * 32 + mt * 16 + r;
#pragma unroll
        for (int half = 0; half < 2; half++) {
            int row = row0 + half * 8;
            int dst = (MODE == M_PERMRES_LN) ? win_to_token(row, shift) : row;
            float s = 0.f, sq = 0.f;
#pragma unroll
            for (int nt2 = 0; nt2 < 4; nt2++) {
                int col = n0 + warp_n * 32 + nt2 * 8 + c * 2;
                float v0 = acc[mt][nt2][half * 2 + 0] + bias[col];
                float v1 = acc[mt][nt2][half * 2 + 1] + bias[col + 1];
                if (MODE == M_RES_LN || MODE == M_PERMRES_LN) {
                    float2 e = *(const float2*)&extra[(size_t)dst * 128 + col];
                    v0 += e.x; v1 += e.y;
                }
                acc[mt][nt2][half * 2 + 0] = v0;
                acc[mt][nt2][half * 2 + 1] = v1;
                s += v0 + v1; sq += v0 * v0 + v1 * v1;
            }
            s  += __shfl_xor_sync(0xffffffffu, s, 1);
            s  += __shfl_xor_sync(0xffffffffu, s, 2);
            sq += __shfl_xor_sync(0xffffffffu, sq, 1);
            sq += __shfl_xor_sync(0xffffffffu, sq, 2);
            rsum[mt][half] = s; rsq[mt][half] = sq;
        }
    }
    __syncthreads();
    float* part = (float*)smg;             // [128 rows][4 warp_n][2]
    if ((lane & 3) == 0) {
#pragma unroll
        for (int mt = 0; mt < 2; mt++)
#pragma unroll
            for (int half = 0; half < 2; half++) {
                int rowloc = warp_m * 32 + mt * 16 + (lane >> 2) + half * 8;
                part[rowloc * 8 + warp_n * 2 + 0] = rsum[mt][half];
                part[rowloc * 8 + warp_n * 2 + 1] = rsq[mt][half];
            }
    }
    __syncthreads();
#pragma unroll
    for (int mt = 0; mt < 2; mt++) {
#pragma unroll
        for (int half = 0; half < 2; half++) {
            int rowloc = warp_m * 32 + mt * 16 + r + half * 8;
            float s  = part[rowloc * 8] + part[rowloc * 8 + 2]
                     + part[rowloc * 8 + 4] + part[rowloc * 8 + 6];
            float sq = part[rowloc * 8 + 1] + part[rowloc * 8 + 3]
                     + part[rowloc * 8 + 5] + part[rowloc * 8 + 7];
            float mu = s * 0.0078125f;
            float var = sq * 0.0078125f - mu * mu;
            float rstd = rsqrtf(var + 1e-5f);
            int row = m0 + rowloc;
            int xdst, wdst;
            if (MODE == M_PERMRES_LN) { xdst = win_to_token(row, shift); wdst = xdst; }
            else                      { xdst = row; wdst = token_to_win(row, shift); }
#pragma unroll
            for (int nt2 = 0; nt2 < 4; nt2++) {
                int col = n0 + warp_n * 32 + nt2 * 8 + c * 2;
                float v0 = acc[mt][nt2][half * 2 + 0];
                float v1 = acc[mt][nt2][half * 2 + 1];
                *(float2*)&C[(size_t)xdst * 128 + col] = make_float2(v0, v1);
                float w0 = (v0 - mu) * rstd * lng[col]     + lnb[col];
                float w1 = (v1 - mu) * rstd * lng[col + 1] + lnb[col + 1];
                *(u32*)&C16[(size_t)wdst * 128 + col] = bf2(w0, w1);
            }
        }
    }
}

// ---------------- fused fusion + LSTM gate kernel (16 warps, 32x32 tiles) ----------------
__device__ __forceinline__ void ml_k128(
    bf16* smg, const bf16* A, const bf16* BT, int m0,
    int tid, int warp_m, int warp_n, int lrow, int lcol,
    float (&acc)[2][4][4])
{
    __syncthreads();   // previous smem users done
    int prr = tid >> 2, pcc = (tid & 3) << 3;
#pragma unroll
    for (int s = 0; s < 4; s++) {
        u32 abase = smem_u32(smg + s * STG_HALFS);
        u32 bbase = abase + 5120 * 2;
        cp16(abase + (u32)(prr * TSTRIDE + pcc) * 2,
             A + (size_t)(m0 + prr) * 128 + s * 32 + pcc);
        cp16(bbase + (u32)(prr * TSTRIDE + pcc) * 2,
             BT + (size_t)prr * 128 + s * 32 + pcc);
    }
    asm volatile("cp.async.commit_group;");
    asm volatile("cp.async.wait_group 0;");
    __syncthreads();
#pragma unroll
    for (int t = 0; t < 4; t++) {
        u32 abase = smem_u32(smg + t * STG_HALFS);
        u32 bbase = abase + 5120 * 2;
#pragma unroll
        for (int ks = 0; ks < 2; ks++) {
            u32 af[2][4];
#pragma unroll
            for (int mt = 0; mt < 2; mt++)
                ldm_x4(af[mt][0], af[mt][1], af[mt][2], af[mt][3],
                       abase + (u32)((warp_m * 32 + mt * 16 + lrow) * TSTRIDE + ks * 16 + lcol) * 2);
            u32 bfr[2][4];
#pragma unroll
            for (int p = 0; p < 2; p++)
                ldm_x4(bfr[p][0], bfr[p][1], bfr[p][2], bfr[p][3],
                       bbase + (u32)((warp_n * 32 + p * 16 + lrow) * TSTRIDE + ks * 16 + lcol) * 2);
#pragma unroll
            for (int p = 0; p < 2; p++)
#pragma unroll
                for (int q = 0; q < 2; q++) {
                    int nt2 = p * 2 + q;
#pragma unroll
                    for (int mt = 0; mt < 2; mt++)
                        mma_bf(acc[mt][nt2], af[mt], bfr[p][q], bfr[p][q + 2]);
                }
        }
    }
}

__global__ void __launch_bounds__(512, 2) fusion_k(
    const bf16* __restrict__ g16, const bf16* __restrict__ loc16,
    const bf16* __restrict__ gfT, const bf16* __restrict__ lfT,
    const bf16* __restrict__ ffT,
    const float* __restrict__ gf_b, const float* __restrict__ lf_b,
    const float* __restrict__ ff_b,
    const float* __restrict__ cx, float* __restrict__ outp)
{
    extern __shared__ bf16 smg[];
    int tid = threadIdx.x;
    int lane = tid & 31, warp = tid >> 5;
    int warp_m = warp & 3, warp_n = warp >> 2;
    int m0 = blockIdx.x << 7;
    int r = lane >> 2, c = lane & 3;
    int lrow = lane & 15;
    int lcol = (lane >> 4) << 3;

    float acc1[2][4][4], acc2[2][4][4];
#pragma unroll
    for (int i = 0; i < 2; i++)
#pragma unroll
        for (int j = 0; j < 4; j++)
#pragma unroll
            for (int q = 0; q < 4; q++) { acc1[i][j][q] = 0.f; acc2[i][j][q] = 0.f; }

    // ML1: g @ gfT ; ML2: loc @ lfT
    ml_k128(smg, g16, gfT, m0, tid, warp_m, warp_n, lrow, lcol, acc1);
    ml_k128(smg, loc16, lfT, m0, tid, warp_m, warp_n, lrow, lcol, acc2);

    __syncthreads();   // all ML2 smem reads done before t overwrites stages
    // t = relu((acc2+lf_b)*(acc1+gf_b)) -> stage A regions (k-tile = warp_n), ldmatrix layout
    {
        u32 abase = smem_u32(smg + warp_n * STG_HALFS);
#pragma unroll
        for (int mt = 0; mt < 2; mt++)
#pragma unroll
            for (int half = 0; half < 2; half++) {
                int row = warp_m * 32 + mt * 16 + r + half * 8;
#pragma unroll
                for (int nt2 = 0; nt2 < 4; nt2++) {
                    int cc = nt2 * 8 + c * 2;          // 0..31 within this k-tile
                    int col = warp_n * 32 + cc;
                    float a0 = acc1[mt][nt2][half * 2 + 0] + gf_b[col];
                    float a1 = acc1[mt][nt2][half * 2 + 1] + gf_b[col + 1];
                    float b0 = acc2[mt][nt2][half * 2 + 0] + lf_b[col];
                    float b1 = acc2[mt][nt2][half * 2 + 1] + lf_b[col + 1];
                    float t0 = a0 * b0, t1 = a1 * b1;
                    t0 = t0 > 0.f ? t0 : 0.f;
                    t1 = t1 > 0.f ? t1 : 0.f;
                    u32 pkv = bf2(t0, t1);
                    asm volatile("st.shared.b32 [%0], %1;"
                                 :: "r"(abase + (u32)(row * TSTRIDE + cc) * 2), "r"(pkv));
                }
            }
    }
    // prefetch ffT into stage B regions
    {
        int prr = tid >> 2, pcc = (tid & 3) << 3;
#pragma unroll
        for (int s = 0; s < 4; s++) {
            u32 bbase = smem_u32(smg + s * STG_HALFS) + 5120 * 2;
            cp16(bbase + (u32)(prr * TSTRIDE + pcc) * 2,
                 ffT + (size_t)prr * 128 + s * 32 + pcc);
        }
    }
    asm volatile("cp.async.commit_group;");
    asm volatile("cp.async.wait_group 0;");
    __syncthreads();

    // ML3: t @ ffT (both resident in smem)
#pragma unroll
    for (int i = 0; i < 2; i++)
#pragma unroll
        for (int j = 0; j < 4; j++)
#pragma unroll
            for (int q = 0; q < 4; q++) acc1[i][j][q] = 0.f;
#pragma unroll
    for (int t = 0; t < 4; t++) {
        u32 abase = smem_u32(smg + t * STG_HALFS);
        u32 bbase = abase + 5120 * 2;
#pragma unroll
        for (int ks = 0; ks < 2; ks++) {
            u32 af[2][4];
#pragma unroll
            for (int mt = 0; mt < 2; mt++)
                ldm_x4(af[mt][0], af[mt][1], af[mt][2], af[mt][3],
                       abase + (u32)((warp_m * 32 + mt * 16 + lrow) * TSTRIDE + ks * 16 + lcol) * 2);
            u32 bfr[2][4];
#pragma unroll
            for (int p = 0; p < 2; p++)
                ldm_x4(bfr[p][0], bfr[p][1], bfr[p][2], bfr[p][3],
                       bbase + (u32)((warp_n * 32 + p * 16 + lrow) * TSTRIDE + ks * 16 + lcol) * 2);
#pragma unroll
            for (int p = 0; p < 2; p++)
#pragma unroll
                for (int q = 0; q < 2; q++) {
                    int nt2 = p * 2 + q;
#pragma unroll
                    for (int mt = 0; mt < 2; mt++)
                        mma_bf(acc1[mt][nt2], af[mt], bfr[p][q], bfr[p][q + 2]);
                }
        }
    }

    // gate epilogue -> d_out (fp32)
#pragma unroll
    for (int mt = 0; mt < 2; mt++) {
        int row0 = m0 + warp_m * 32 + mt * 16 + r;
#pragma unroll
        for (int half = 0; half < 2; half++) {
            int row = row0 + half * 8;
#pragma unroll
            for (int nt2 = 0; nt2 < 4; nt2++) {
                int col = warp_n * 32 + nt2 * 8 + c * 2;
                float v0 = acc1[mt][nt2][half * 2 + 0] + ff_b[col];
                float v1 = acc1[mt][nt2][half * 2 + 1] + ff_b[col + 1];
                size_t off = (size_t)row * 128 + col;
                float2 e = *(const float2*)&cx[off];
                float g0 = 1.f / (1.f + expf(-v0));
                float g1 = 1.f / (1.f + expf(-v1));
                float cy0 = g0 * (e.x + tanhf(v0));
                float cy1 = g1 * (e.y + tanhf(v1));
                *(float2*)&outp[off] = make_float2(g0 * tanhf(cy0), g1 * tanhf(cy1));
            }
        }
    }
}

// ---------------- tensor-core window attention ----------------
#define ATT_STRIDE 136    // 128 d halfs + 8 pad (272 B rows)
#define ATT_SMEM   (3 * 64 * ATT_STRIDE * 2 + 900 * 4)

__global__ void __launch_bounds__(256) attn5(
    const bf16* __restrict__ qkv, const float* __restrict__ rp,
    bf16* __restrict__ out, int shift)
{
    extern __shared__ char smr[];
    bf16* qs = (bf16*)smr;
    bf16* ks = qs + 64 * ATT_STRIDE;
    bf16* vs = ks + 64 * ATT_STRIDE;
    float* rps = (float*)(vs + 64 * ATT_STRIDE);
    int tid = threadIdx.x;
    int lane = tid & 31, warp = tid >> 5;
    int bw = blockIdx.x;
    const float SCALE = 0.17677669529663687f;

    const bf16* base = qkv + (size_t)bw * 64 * 384;
#pragma unroll
    for (int i = 0; i < 12; i++) {
        int idx = tid + i * 256;
        int n = idx / 48, part = idx % 48;
        uint4 val = *(const uint4*)(base + (size_t)n * 384 + part * 8);
        bf16* dstp = (part < 16) ? qs : (part < 32) ? ks : vs;
        *(uint4*)&dstp[n * ATT_STRIDE + (part & 15) * 8] = val;
    }
    for (int i = tid; i < 900; i += 256) rps[i] = rp[i];
    __syncthreads();

    int h = warp >> 1;
    int m0 = (warp & 1) * 32;
    int cb = h * 32;
    int lrow = lane & 15;
    int lcol = (lane >> 4) << 3;

    u32 aq[2][2][4];
#pragma unroll
    for (int mt = 0; mt < 2; mt++)
#pragma unroll
        for (int kt = 0; kt < 2; kt++)
            ldm_x4(aq[mt][kt][0], aq[mt][kt][1], aq[mt][kt][2], aq[mt][kt][3],
                   smem_u32(&qs[(m0 + 16 * mt + lrow) * ATT_STRIDE + cb + 16 * kt + lcol]));

    float sacc[2][8][4];
#pragma unroll
    for (int mt = 0; mt < 2; mt++)
#pragma unroll
        for (int nt = 0; nt < 8; nt++)
#pragma unroll
            for (int q = 0; q < 4; q++) sacc[mt][nt][q] = 0.f;

#pragma unroll
    for (int ntp = 0; ntp < 4; ntp++)
#pragma unroll
        for (int kt = 0; kt < 2; kt++) {
            u32 b0, b1, b2, b3;
            ldm_x4(b0, b1, b2, b3,
                   smem_u32(&ks[(16 * ntp + lrow) * ATT_STRIDE + cb + 16 * kt + lcol]));
#pragma unroll
            for (int mt = 0; mt < 2; mt++) {
                mma_bf(sacc[mt][2 * ntp],     aq[mt][kt], b0, b2);
                mma_bf(sacc[mt][2 * ntp + 1], aq[mt][kt], b1, b3);
            }
        }

    int widx = bw & 63;
    int wh = widx >> 3, ww = widx & 7;
#pragma unroll
    for (int mt = 0; mt < 2; mt++)
#pragma unroll
        for (int q = 0; q < 4; q++) {
            int t1 = m0 + 16 * mt + (lane >> 2) + ((q >> 1) << 3);
            int r1 = t1 >> 3, s1 = t1 & 7;
            int h1 = wh * 8 + r1, w1 = ww * 8 + s1;
            int img1 = (h1 < 56 ? 0 : (h1 < 60 ? 1 : 2)) * 3 + (w1 < 56 ? 0 : (w1 < 60 ? 1 : 2));
#pragma unroll
            for (int nt = 0; nt < 8; nt++) {
                int t2 = nt * 8 + 2 * (lane & 3) + (q & 1);
                int r2 = t2 >> 3, s2 = t2 & 7;
                float v = sacc[mt][nt][q] * SCALE
                        + rps[((r1 - r2 + 7) * 15 + (s1 - s2 + 7)) * 4 + h];
                if (shift) {
                    int h2 = wh * 8 + r2, w2 = ww * 8 + s2;
                    int img2 = (h2 < 56 ? 0 : (h2 < 60 ? 1 : 2)) * 3 + (w2 < 56 ? 0 : (w2 < 60 ? 1 : 2));
                    if (img1 != img2) v -= 100.f;
                }
                sacc[mt][nt][q] = v;
            }
        }

#pragma unroll
    for (int mt = 0; mt < 2; mt++)
#pragma unroll
        for (int half = 0; half < 2; half++) {
            float mx = -1e30f;
#pragma unroll
            for (int nt = 0; nt < 8; nt++) {
                mx = fmaxf(mx, sacc[mt][nt][2 * half]);
                mx = fmaxf(mx, sacc[mt][nt][2 * half + 1]);
            }
            mx = fmaxf(mx, __shfl_xor_sync(0xffffffffu, mx, 1));
            mx = fmaxf(mx, __shfl_xor_sync(0xffffffffu, mx, 2));
            float sum = 0.f;
#pragma unroll
            for (int nt = 0; nt < 8; nt++) {
#pragma unroll
                for (int qq = 0; qq < 2; qq++) {
                    float e = __expf(sacc[mt][nt][2 * half + qq] - mx);
                    sacc[mt][nt][2 * half + qq] = e;
                    sum += e;
                }
            }
            sum += __shfl_xor_sync(0xffffffffu, sum, 1);
            sum += __shfl_xor_sync(0xffffffffu, sum, 2);
            float inv = 1.f / sum;
#pragma unroll
            for (int nt = 0; nt < 8; nt++) {
                sacc[mt][nt][2 * half] *= inv;
                sacc[mt][nt][2 * half + 1] *= inv;
            }
        }

    u32 pa[2][4][4];
#pragma unroll
    for (int mt = 0; mt < 2; mt++)
#pragma unroll
        for (int j = 0; j < 4; j++) {
            pa[mt][j][0] = bf2(sacc[mt][2 * j][0],     sacc[mt][2 * j][1]);
            pa[mt][j][1] = bf2(sacc[mt][2 * j][2],     sacc[mt][2 * j][3]);
            pa[mt][j][2] = bf2(sacc[mt][2 * j + 1][0], sacc[mt][2 * j + 1][1]);
            pa[mt][j][3] = bf2(sacc[mt][2 * j + 1][2], sacc[mt][2 * j + 1][3]);
        }

    float oacc[2][4][4];
#pragma unroll
    for (int mt = 0; mt < 2; mt++)
#pragma unroll
        for (int nt2 = 0; nt2 < 4; nt2++)
#pragma unroll
            for (int q = 0; q < 4; q++) oacc[mt][nt2][q] = 0.f;

#pragma unroll
    for (int j = 0; j < 4; j++)
#pragma unroll
        for (int ntp = 0; ntp < 2; ntp++) {
            u32 b0, b1, b2, b3;
            ldmt_x4(b0, b1, b2, b3,
                    smem_u32(&vs[(16 * j + lrow) * ATT_STRIDE + cb + 16 * ntp + lcol]));
#pragma unroll
            for (int mt = 0; mt < 2; mt++) {
                mma_bf(oacc[mt][2 * ntp],     pa[mt][j], b0, b1);
                mma_bf(oacc[mt][2 * ntp + 1], pa[mt][j], b2, b3);
            }
        }

#pragma unroll
    for (int mt = 0; mt < 2; mt++) {
        int row0 = bw * 64 + m0 + 16 * mt + (lane >> 2);
        int col  = cb + 2 * (lane & 3);
#pragma unroll
        for (int nt2 = 0; nt2 < 4; nt2++) {
            *(u32*)&out[(size_t)row0 * 128 + col + nt2 * 8]       = bf2(oacc[mt][nt2][0], oacc[mt][nt2][1]);
            *(u32*)&out[(size_t)(row0 + 8) * 128 + col + nt2 * 8] = bf2(oacc[mt][nt2][2], oacc[mt][nt2][3]);
        }
    }
}

// ---------------- fused deformable-conv branch (offset/mask conv + gather) ----------------
__global__ void __launch_bounds__(256) local_k(
    const float* __restrict__ xt,
    const float* __restrict__ ow, const float* __restrict__ ob,
    const float* __restrict__ mw, const float* __restrict__ mb,
    bf16* __restrict__ outp)
{
    __shared__ float rows[34][128];
    __shared__ float wo_s[1152], wm_s[1152];
    __shared__ int   s_fp[3][32];
    __shared__ float s_a0[3][32], s_a1[3][32];
    __shared__ bf16  smout[32][130];
    int b  = blockIdx.x >> 7;
    int l0 = (blockIdx.x & 127) << 5;
    int tid = threadIdx.x;
    int warp = tid >> 5, lane = tid & 31;

    for (int i = tid; i < 1152; i += 256) { wo_s[i] = ow[i]; wm_s[i] = mw[i]; }
#pragma unroll
    for (int i = 0; i < 5; i++) {
        int idx = i * 256 + tid;             // float4 ids, need 34*32 = 1088
        if (idx < 1088) {
            int rr = idx >> 5, c4 = (idx & 31) << 2;
            int l = l0 - 1 + rr;
            if (l >= 0 && l < 4096)
                *(float4*)&rows[rr][c4] = *(const float4*)(xt + ((size_t)b * 4096 + l) * 128 + c4);
        }
    }
    __syncthreads();

    int c0 = lane << 2;
#pragma unroll
    for (int it = 0; it < 4; it++) {
        int tl = warp * 4 + it;              // local token 0..31
        int l = l0 + tl;
        float so[3] = {0.f, 0.f, 0.f}, sm[3] = {0.f, 0.f, 0.f};
#pragma unroll
        for (int j = 0; j < 3; j++) {
            int ll = l + j - 1;
            if (ll < 0 || ll > 4095) continue;
            float4 xv = *(const float4*)&rows[tl + j][c0];
#pragma unroll
            for (int k = 0; k < 3; k++) {
                const float* owp = wo_s + k * 384 + j;
                const float* mwp = wm_s + k * 384 + j;
                so[k] += xv.x * owp[(c0 + 0) * 3] + xv.y * owp[(c0 + 1) * 3]
                       + xv.z * owp[(c0 + 2) * 3] + xv.w * owp[(c0 + 3) * 3];
                sm[k] += xv.x * mwp[(c0 + 0) * 3] + xv.y * mwp[(c0 + 1) * 3]
                       + xv.z * mwp[(c0 + 2) * 3] + xv.w * mwp[(c0 + 3) * 3];
            }
        }
#pragma unroll
        for (int o = 16; o > 0; o >>= 1) {
#pragma unroll
            for (int k = 0; k < 3; k++) {
                so[k] += __shfl_xor_sync(0xffffffffu, so[k], o);
                sm[k] += __shfl_xor_sync(0xffffffffu, sm[k], o);
            }
        }
        if (lane < 3) {
            int k = lane;
            float off = ob[k] + so[k];
            float mk  = mb[k] + sm[k];
            float mask = 1.f / (1.f + expf(-mk));
            float pos = fminf(fmaxf((float)l + off, 0.f), 4095.f);
            float fpf = floorf(pos);
            int f = (int)fpf;
            float alpha = pos - fpf;
            s_fp[k][tl] = f;
            s_a0[k][tl] = (1.f - alpha) * mask;
            s_a1[k][tl] = alpha * mask;
        }
    }
    __syncthreads();

    // phase 2: gather + bf16, transpose via smem, coalesced (B,C,L) write
#pragma unroll
    for (int i = 0; i < 16; i++) {
        int idx = i * 256 + tid;          // 0..4095
        int dl = idx >> 7, c = idx & 127;
        float o = 0.f;
#pragma unroll
        for (int k = 0; k < 3; k++) {
            int f  = s_fp[k][dl];
            int cp = min(f + 1, 4095);
            o += xt[((size_t)b * 4096 + f)  * 128 + c] * s_a0[k][dl]
               + xt[((size_t)b * 4096 + cp) * 128 + c] * s_a1[k][dl];
        }
        smout[dl][c] = __float2bfloat16_rn(o);
    }
    __syncthreads();
#pragma unroll
    for (int i = 0; i < 16; i++) {
        int idx = i * 256 + tid;
        int c = idx >> 5, dl = idx & 31;
        outp[(size_t)b * 524288 + (size_t)c * 4096 + l0 + dl] = smout[dl][c];
    }
}

// ---------------- host launcher ----------------
extern "C" void kernel_launch(void* const* d_in, const int* in_sizes, int n_in,
                              void* d_out, int out_size)
{
    const float* xt    = (const float*)d_in[0];
    const float* hx    = (const float*)d_in[1];
    const float* cx    = (const float*)d_in[2];
    const float* red_w = (const float*)d_in[3];
    const float* red_b = (const float*)d_in[4];
    const float* n1g   = (const float*)d_in[5];
    const float* n1b   = (const float*)d_in[6];
    const float* qkvw  = (const float*)d_in[7];
    const float* qkvb  = (const float*)d_in[8];
    const float* rp    = (const float*)d_in[9];
    const float* pw    = (const float*)d_in[10];
    const float* pb    = (const float*)d_in[11];
    const float* n2g   = (const float*)d_in[12];
    const float* n2b   = (const float*)d_in[13];
    const float* f1w   = (const float*)d_in[14];
    const float* f1b   = (const float*)d_in[15];
    const float* f2w   = (const float*)d_in[16];
    const float* f2b   = (const float*)d_in[17];
    const float* off_w = (const float*)d_in[18];
    const float* off_b = (const float*)d_in[19];
    const float* msk_w = (const float*)d_in[20];
    const float* msk_b = (const float*)d_in[21];
    const float* lf_w  = (const float*)d_in[22];
    const float* lf_b  = (const float*)d_in[23];
    const float* gf_w  = (const float*)d_in[24];
    const float* gf_b  = (const float*)d_in[25];
    const float* ff_w  = (const float*)d_in[26];
    const float* ff_b  = (const float*)d_in[27];

    float* px;
    bf16 *pbig16, *pxw16, *patt16, *ploc16, *px16;
    bf16 *predT, *pqkvT, *ppwT, *pf1T, *pf2T, *plfT, *pgfT, *pffT;
    cudaGetSymbolAddress((void**)&px,    d_x);
    cudaGetSymbolAddress((void**)&pbig16, g_big16);
    cudaGetSymbolAddress((void**)&pxw16, g_xw16);
    cudaGetSymbolAddress((void**)&patt16, g_att16);
    cudaGetSymbolAddress((void**)&ploc16, g_loc16);
    cudaGetSymbolAddress((void**)&px16,  g_x16);
    cudaGetSymbolAddress((void**)&predT, g_redT);
    cudaGetSymbolAddress((void**)&pqkvT, g_qkvT);
    cudaGetSymbolAddress((void**)&ppwT,  g_pwT);
    cudaGetSymbolAddress((void**)&pf1T,  g_f1T);
    cudaGetSymbolAddress((void**)&pf2T,  g_f2T);
    cudaGetSymbolAddress((void**)&plfT,  g_lfT);
    cudaGetSymbolAddress((void**)&pgfT,  g_gfT);
    cudaGetSymbolAddress((void**)&pffT,  g_ffT);

    cudaFuncSetAttribute(gemm_tc<M_PLAIN>,      cudaFuncAttributeMaxDynamicSharedMemorySize, GEMM_SMEM);
    cudaFuncSetAttribute(gemm_tc<M_GELU>,       cudaFuncAttributeMaxDynamicSharedMemorySize, GEMM_SMEM);
    cudaFuncSetAttribute(gemm_tc<M_RES>,        cudaFuncAttributeMaxDynamicSharedMemorySize, GEMM_SMEM);
    cudaFuncSetAttribute(gemm_tc<M_PLAIN_LN>,   cudaFuncAttributeMaxDynamicSharedMemorySize, GEMM_SMEM);
    cudaFuncSetAttribute(gemm_tc<M_RES_LN>,     cudaFuncAttributeMaxDynamicSharedMemorySize, GEMM_SMEM);
    cudaFuncSetAttribute(gemm_tc<M_PERMRES_LN>, cudaFuncAttributeMaxDynamicSharedMemorySize, GEMM_SMEM);
    cudaFuncSetAttribute(gemm_tc<M_CONCAT_LN>,  cudaFuncAttributeMaxDynamicSharedMemorySize, GEMM_SMEM);
    cudaFuncSetAttribute(fusion_k,              cudaFuncAttributeMaxDynamicSharedMemorySize, GEMM_SMEM);
    cudaFuncSetAttribute(attn5,                 cudaFuncAttributeMaxDynamicSharedMemorySize, ATT_SMEM);

    // weight transpose-convert (fp32 KxN -> bf16 NxK)
    WPack wp;
    wp.e[0]  = { red_w,           predT,           256, 128 };
    wp.e[1]  = { qkvw,            pqkvT,           128, 384 };
    wp.e[2]  = { qkvw + 49152,    pqkvT + 49152,   128, 384 };
    wp.e[3]  = { pw,              ppwT,            128, 128 };
    wp.e[4]  = { pw + 16384,      ppwT + 16384,    128, 128 };
    wp.e[5]  = { f1w,             pf1T,            128, 512 };
    wp.e[6]  = { f1w + 65536,     pf1T + 65536,    128, 512 };
    wp.e[7]  = { f2w,             pf2T,            512, 128 };
    wp.e[8]  = { f2w + 65536,     pf2T + 65536,    512, 128 };
    wp.e[9]  = { lf_w,            plfT,            128, 128 };
    wp.e[10] = { gf_w,            pgfT,            128, 128 };
    wp.e[11] = { ff_w,            pffT,            128, 128 };
    wconv_k<<<dim3(48, 12), 256>>>(wp);

    // local (deformable) branch — fused offsets + gather
    local_k<<<Bn * 128, 256>>>(xt, off_w, off_b, msk_w, msk_b, ploc16);

    // global branch: reduce GEMM with fused concat input + fused LN1(block0, shift 0)
    gemm_tc<M_CONCAT_LN><<<dim3(1, 256), 512, GEMM_SMEM>>>(
        nullptr, predT, red_b, nullptr, px, pxw16, n1g, n1b, 128, 256, 0, xt, hx);

    for (int i = 0; i < 2; i++) {
        int shift = i ? 4 : 0;
        gemm_tc<M_PLAIN><<<dim3(3, 256), 512, GEMM_SMEM>>>(
            pxw16, pqkvT + i * 49152, qkvb + i * 384, nullptr,
            nullptr, pbig16, nullptr, nullptr, 384, 128, 0, nullptr, nullptr);
        attn5<<<512, 256, ATT_SMEM>>>(pbig16, rp + i * 900, patt16, shift);
        gemm_tc<M_PERMRES_LN><<<dim3(1, 256), 512, GEMM_SMEM>>>(
            patt16, ppwT + i * 16384, pb + i * 128, px,
            px, pxw16, n2g + i * 128, n2b + i * 128, 128, 128, shift, nullptr, nullptr);
        gemm_tc<M_GELU><<<dim3(4, 256), 512, GEMM_SMEM>>>(
            pxw16, pf1T + i * 65536, f1b + i * 512, nullptr,
            nullptr, pbig16, nullptr, nullptr, 512, 128, 0, nullptr, nullptr);
        if (i == 0) {
            gemm_tc<M_RES_LN><<<dim3(1, 256), 512, GEMM_SMEM>>>(
                pbig16, pf2T, f2b, px,
                px, pxw16, n1g + 128, n1b + 128, 128, 512, 4, nullptr, nullptr);
        } else {
            gemm_tc<M_RES><<<dim3(1, 256), 512, GEMM_SMEM>>>(
                pbig16, pf2T + 65536, f2b + 128, px,
                px, px16, nullptr, nullptr, 128, 512, 0, nullptr, nullptr);
        }
    }

    // fused fusion + LSTM gate
    fusion_k<<<256, 512, GEMM_SMEM>>>(px16, ploc16, pgfT, plfT, pffT,
                                      gf_b, lf_b, ff_b, cx, (float*)d_out);
}

// round 14
// speedup vs baseline: 1.5471x; 1.0308x over previous
#include <cuda_runtime.h>
#include <cuda_bf16.h>
#include <math.h>

// Problem constants
#define Bn   8
#define Ln   4096
#define Cn   128
#define BL   32768            // B*L rows

typedef unsigned int u32;
typedef unsigned long long u64;
typedef __nv_bfloat16 bf16;

// ---------------- helpers ----------------
__device__ __forceinline__ u32 smem_u32(const void* p) {
    u32 a;
    asm("{ .reg .u64 t; cvta.to.shared.u64 t, %1; cvt.u32.u64 %0, t; }" : "=r"(a) : "l"(p));
    return a;
}
__device__ __forceinline__ void cp16(u32 dst, const void* src) {
    size_t g = __cvta_generic_to_global(src);
    asm volatile("cp.async.cg.shared.global [%0], [%1], 16;" :: "r"(dst), "l"(g));
}
__device__ __forceinline__ void ldm_x4(u32& r0, u32& r1, u32& r2, u32& r3, u32 addr) {
    asm volatile("ldmatrix.sync.aligned.m8n8.x4.shared.b16 {%0,%1,%2,%3}, [%4];"
                 : "=r"(r0), "=r"(r1), "=r"(r2), "=r"(r3) : "r"(addr));
}
__device__ __forceinline__ void ldmt_x4(u32& r0, u32& r1, u32& r2, u32& r3, u32 addr) {
    asm volatile("ldmatrix.sync.aligned.m8n8.x4.trans.shared.b16 {%0,%1,%2,%3}, [%4];"
                 : "=r"(r0), "=r"(r1), "=r"(r2), "=r"(r3) : "r"(addr));
}
__device__ __forceinline__ u32 bf2(float a, float b) {
    __nv_bfloat162 h;
    h.x = __float2bfloat16_rn(a);
    h.y = __float2bfloat16_rn(b);
    return *(u32*)&h;
}
__device__ __forceinline__ void mma_bf(float* c, const u32* a, u32 b0, u32 b1) {
    asm volatile(
        "mma.sync.aligned.m16n8k16.row.col.f32.bf16.bf16.f32 "
        "{%0,%1,%2,%3},{%4,%5,%6,%7},{%8,%9},{%0,%1,%2,%3};"
        : "+f"(c[0]), "+f"(c[1]), "+f"(c[2]), "+f"(c[3])
        : "r"(a[0]), "r"(a[1]), "r"(a[2]), "r"(a[3]), "r"(b0), "r"(b1));
}

// ---------------- scratch (device globals; no allocs allowed) ----------------
__device__ float d_x   [BL * Cn];      // running stream (fp32)
__device__ bf16  g_big16[BL * 512];    // qkv / MLP hidden (bf16)
__device__ bf16  g_xw16 [BL * Cn];     // LN output (bf16)
__device__ bf16  g_att16[BL * Cn];     // attention out (bf16)
__device__ bf16  g_loc16[BL * Cn];     // deform out (bf16, (B,C,L) flat)
__device__ bf16  g_x16  [BL * Cn];     // final g (bf16)
// transposed bf16 weights (N x K row-major)
__device__ bf16  g_redT[128 * 256];
__device__ bf16  g_qkvT[2 * 384 * 128];
__device__ bf16  g_pwT [2 * 128 * 128];
__device__ bf16  g_f1T [2 * 512 * 128];
__device__ bf16  g_f2T [2 * 128 * 512];
__device__ bf16  g_lfT [128 * 128];
__device__ bf16  g_gfT [128 * 128];
__device__ bf16  g_ffT [128 * 128];

// window-layout row m  ->  token index (b*L + ho*64 + wo)
__device__ __forceinline__ int win_to_token(int m, int shift) {
    int n    = m & 63;
    int bw   = m >> 6;
    int widx = bw & 63;
    int b    = bw >> 6;
    int wh = widx >> 3, ww = widx & 7;
    int r = n >> 3, s = n & 7;
    int ho = (wh * 8 + r + shift) & 63;
    int wo = (ww * 8 + s + shift) & 63;
    return (b << 12) + (ho << 6) + wo;
}
// token index -> window-layout row (exact inverse)
__device__ __forceinline__ int token_to_win(int t, int shift) {
    int b = t >> 12, rem = t & 4095;
    int ho = rem >> 6, wo = rem & 63;
    int u = (ho - shift) & 63, v = (wo - shift) & 63;
    int wh = u >> 3, r = u & 7;
    int ww = v >> 3, s = v & 7;
    return (((b << 6) + (wh << 3) + ww) << 6) + (r << 3) + s;
}

// ---------------- weight transpose-convert: (K x N fp32) -> (N x K bf16) ----------------
struct WEnt { const float* src; bf16* dst; int K; int N; };
struct WPack { WEnt e[12]; };

__global__ void __launch_bounds__(256) wconv_k(WPack p) {
    WEnt w = p.e[blockIdx.y];
    int total = w.K * w.N;
    for (int i = blockIdx.x * 256 + threadIdx.x; i < total; i += gridDim.x * 256) {
        int n = i / w.K, k = i - n * w.K;
        w.dst[i] = __float2bfloat16_rn(w.src[(size_t)k * w.N + n]);
    }
}

// ---------------- bf16 tensor-core GEMM: 128x128 tile, 16 warps (32x32/warp) ---------------
// K and N are compile-time: full unroll, static addressing, static wait_group predicates.
enum { M_PLAIN = 0, M_GELU, M_RES, M_PERMRES,
       M_PLAIN_LN, M_RES_LN, M_PERMRES_LN, M_CONCAT_LN };

#define TSTRIDE 40            // 32 k halfs + 8 pad (80 B rows)
#define STG_HALFS 10240       // per stage: A 5120 halfs + B 5120 halfs (20480 B)
#define GEMM_SMEM (4 * STG_HALFS * 2)   // 81920 B

template <int MODE, int NN, int KK>
__global__ void __launch_bounds__(512, 2) gemm_tc(
    const bf16* __restrict__ A, const bf16* __restrict__ BT,
    const float* __restrict__ bias, const float* __restrict__ extra,
    float* __restrict__ C, bf16* __restrict__ C16,
    const float* __restrict__ lng, const float* __restrict__ lnb,
    int shift,
    const float* __restrict__ Ax, const float* __restrict__ Ah)
{
    extern __shared__ bf16 smg[];
    int tid = threadIdx.x;
    int lane = tid & 31, warp = tid >> 5;       // warp 0..15
    int warp_m = warp & 3, warp_n = warp >> 2;  // 4 (M) x 4 (N), 32x32 tiles
    int m0 = blockIdx.y << 7, n0 = blockIdx.x << 7;
    int r = lane >> 2, c = lane & 3;

    const bool LN = (MODE == M_PLAIN_LN || MODE == M_RES_LN ||
                     MODE == M_PERMRES_LN || MODE == M_CONCAT_LN);

    float acc[2][4][4];
#pragma unroll
    for (int i = 0; i < 2; i++)
#pragma unroll
        for (int j = 0; j < 4; j++)
#pragma unroll
            for (int q = 0; q < 4; q++) acc[i][j][q] = 0.f;

    const int prr = tid >> 2;                    // 0..127
    const int pcc = (tid & 3) << 3;              // 0,8,16,24
    auto prefetch = [&](int k0, int s) {
        u32 abase = smem_u32(smg + s * STG_HALFS);
        u32 bbase = abase + 5120 * 2;
        if (MODE == M_CONCAT_LN) {
            // fused concat(xt,hx) -> bf16 staging (fp32 LDG + cvt + STS)
            int gk = k0 + pcc;
            const float* srcp = (gk < 128) ? Ax + (size_t)(m0 + prr) * 128 + gk
                                           : Ah + (size_t)(m0 + prr) * 128 + gk - 128;
            float4 v0 = *(const float4*)srcp;
            float4 v1 = *(const float4*)(srcp + 4);
            u32 w0 = bf2(v0.x, v0.y), w1 = bf2(v0.z, v0.w);
            u32 w2 = bf2(v1.x, v1.y), w3 = bf2(v1.z, v1.w);
            asm volatile("st.shared.v4.b32 [%0], {%1,%2,%3,%4};"
                         :: "r"(abase + (u32)(prr * TSTRIDE + pcc) * 2),
                            "r"(w0), "r"(w1), "r"(w2), "r"(w3));
        } else {
            cp16(abase + (u32)(prr * TSTRIDE + pcc) * 2,
                 A + (size_t)(m0 + prr) * KK + k0 + pcc);
        }
        cp16(bbase + (u32)(prr * TSTRIDE + pcc) * 2,
             BT + (size_t)(n0 + prr) * KK + k0 + pcc);
        asm volatile("cp.async.commit_group;");
    };

    int lrow = lane & 15;
    int lcol = (lane >> 4) << 3;                 // 0 or 8 halfs

    constexpr int ntk = KK >> 5;
    prefetch(0, 0);
    if (ntk > 1) prefetch(32, 1);
#pragma unroll
    for (int t = 0; t < ntk; t++) {
        if (t + 2 < ntk) prefetch((t + 2) << 5, (t + 2) & 3);
        if (t < ntk - 2)       asm volatile("cp.async.wait_group 2;");
        else if (t == ntk - 2) asm volatile("cp.async.wait_group 1;");
        else                   asm volatile("cp.async.wait_group 0;");
        __syncthreads();

        u32 abase = smem_u32(smg + (t & 3) * STG_HALFS);
        u32 bbase = abase + 5120 * 2;
#pragma unroll
        for (int ks = 0; ks < 2; ks++) {
            u32 af[2][4];
#pragma unroll
            for (int mt = 0; mt < 2; mt++)
                ldm_x4(af[mt][0], af[mt][1], af[mt][2], af[mt][3],
                       abase + (u32)((warp_m * 32 + mt * 16 + lrow) * TSTRIDE + ks * 16 + lcol) * 2);
            u32 bfr[2][4];
#pragma unroll
            for (int p = 0; p < 2; p++)
                ldm_x4(bfr[p][0], bfr[p][1], bfr[p][2], bfr[p][3],
                       bbase + (u32)((warp_n * 32 + p * 16 + lrow) * TSTRIDE + ks * 16 + lcol) * 2);
#pragma unroll
            for (int p = 0; p < 2; p++)
#pragma unroll
                for (int q = 0; q < 2; q++) {
                    int nt2 = p * 2 + q;
                    u32 b0 = bfr[p][q], b1 = bfr[p][q + 2];
#pragma unroll
                    for (int mt = 0; mt < 2; mt++)
                        mma_bf(acc[mt][nt2], af[mt], b0, b1);
                }
        }
    }

    if (!LN) {
#pragma unroll
        for (int mt = 0; mt < 2; mt++) {
            int row0 = m0 + warp_m * 32 + mt * 16 + r;
#pragma unroll
            for (int half = 0; half < 2; half++) {
                int row = row0 + half * 8;
                int dst = (MODE == M_PERMRES) ? win_to_token(row, shift) : row;
#pragma unroll
                for (int nt2 = 0; nt2 < 4; nt2++) {
                    int col = n0 + warp_n * 32 + nt2 * 8 + c * 2;
                    float v0 = acc[mt][nt2][half * 2 + 0] + bias[col];
                    float v1 = acc[mt][nt2][half * 2 + 1] + bias[col + 1];
                    size_t off = (size_t)dst * NN + col;
                    if (MODE == M_GELU) {
                        v0 = 0.5f * v0 * (1.f + erff(v0 * 0.70710678118654752f));
                        v1 = 0.5f * v1 * (1.f + erff(v1 * 0.70710678118654752f));
                    } else if (MODE == M_RES || MODE == M_PERMRES) {
                        float2 e = *(const float2*)&extra[off];
                        v0 += e.x; v1 += e.y;
                    }
                    if (C)   *(float2*)&C[off] = make_float2(v0, v1);
                    if (C16) *(u32*)&C16[off]  = bf2(v0, v1);
                }
            }
        }
        return;
    }

    // ---- fused-LN epilogue (NN == 128) ----
    float rsum[2][2], rsq[2][2];
#pragma unroll
    for (int mt = 0; mt < 2; mt++) {
        int row0 = m0 + warp_m * 32 + mt * 16 + r;
#pragma unroll
        for (int half = 0; half < 2; half++) {
            int row = row0 + half * 8;
            int dst = (MODE == M_PERMRES_LN) ? win_to_token(row, shift) : row;
            float s = 0.f, sq = 0.f;
#pragma unroll
            for (int nt2 = 0; nt2 < 4; nt2++) {
                int col = n0 + warp_n * 32 + nt2 * 8 + c * 2;
                float v0 = acc[mt][nt2][half * 2 + 0] + bias[col];
                float v1 = acc[mt][nt2][half * 2 + 1] + bias[col + 1];
                if (MODE == M_RES_LN || MODE == M_PERMRES_LN) {
                    float2 e = *(const float2*)&extra[(size_t)dst * 128 + col];
                    v0 += e.x; v1 += e.y;
                }
                acc[mt][nt2][half * 2 + 0] = v0;
                acc[mt][nt2][half * 2 + 1] = v1;
                s += v0 + v1; sq += v0 * v0 + v1 * v1;
            }
            s  += __shfl_xor_sync(0xffffffffu, s, 1);
            s  += __shfl_xor_sync(0xffffffffu, s, 2);
            sq += __shfl_xor_sync(0xffffffffu, sq, 1);
            sq += __shfl_xor_sync(0xffffffffu, sq, 2);
            rsum[mt][half] = s; rsq[mt][half] = sq;
        }
    }
    __syncthreads();
    float* part = (float*)smg;             // [128 rows][4 warp_n][2]
    if ((lane & 3) == 0) {
#pragma unroll
        for (int mt = 0; mt < 2; mt++)
#pragma unroll
            for (int half = 0; half < 2; half++) {
                int rowloc = warp_m * 32 + mt * 16 + (lane >> 2) + half * 8;
                part[rowloc * 8 + warp_n * 2 + 0] = rsum[mt][half];
                part[rowloc * 8 + warp_n * 2 + 1] = rsq[mt][half];
            }
    }
    __syncthreads();
#pragma unroll
    for (int mt = 0; mt < 2; mt++) {
#pragma unroll
        for (int half = 0; half < 2; half++) {
            int rowloc = warp_m * 32 + mt * 16 + r + half * 8;
            float s  = part[rowloc * 8] + part[rowloc * 8 + 2]
                     + part[rowloc * 8 + 4] + part[rowloc * 8 + 6];
            float sq = part[rowloc * 8 + 1] + part[rowloc * 8 + 3]
                     + part[rowloc * 8 + 5] + part[rowloc * 8 + 7];
            float mu = s * 0.0078125f;
            float var = sq * 0.0078125f - mu * mu;
            float rstd = rsqrtf(var + 1e-5f);
            int row = m0 + rowloc;
            int xdst, wdst;
            if (MODE == M_PERMRES_LN) { xdst = win_to_token(row, shift); wdst = xdst; }
            else                      { xdst = row; wdst = token_to_win(row, shift); }
#pragma unroll
            for (int nt2 = 0; nt2 < 4; nt2++) {
                int col = n0 + warp_n * 32 + nt2 * 8 + c * 2;
                float v0 = acc[mt][nt2][half * 2 + 0];
                float v1 = acc[mt][nt2][half * 2 + 1];
                *(float2*)&C[(size_t)xdst * 128 + col] = make_float2(v0, v1);
                float w0 = (v0 - mu) * rstd * lng[col]     + lnb[col];
                float w1 = (v1 - mu) * rstd * lng[col + 1] + lnb[col + 1];
                *(u32*)&C16[(size_t)wdst * 128 + col] = bf2(w0, w1);
            }
        }
    }
}

// ---------------- fused fusion + LSTM gate kernel (16 warps, 32x32 tiles) ----------------
__device__ __forceinline__ void ml_k128(
    bf16* smg, const bf16* A, const bf16* BT, int m0,
    int tid, int warp_m, int warp_n, int lrow, int lcol,
    float (&acc)[2][4][4])
{
    __syncthreads();   // previous smem users done
    int prr = tid >> 2, pcc = (tid & 3) << 3;
#pragma unroll
    for (int s = 0; s < 4; s++) {
        u32 abase = smem_u32(smg + s * STG_HALFS);
        u32 bbase = abase + 5120 * 2;
        cp16(abase + (u32)(prr * TSTRIDE + pcc) * 2,
             A + (size_t)(m0 + prr) * 128 + s * 32 + pcc);
        cp16(bbase + (u32)(prr * TSTRIDE + pcc) * 2,
             BT + (size_t)prr * 128 + s * 32 + pcc);
    }
    asm volatile("cp.async.commit_group;");
    asm volatile("cp.async.wait_group 0;");
    __syncthreads();
#pragma unroll
    for (int t = 0; t < 4; t++) {
        u32 abase = smem_u32(smg + t * STG_HALFS);
        u32 bbase = abase + 5120 * 2;
#pragma unroll
        for (int ks = 0; ks < 2; ks++) {
            u32 af[2][4];
#pragma unroll
            for (int mt = 0; mt < 2; mt++)
                ldm_x4(af[mt][0], af[mt][1], af[mt][2], af[mt][3],
                       abase + (u32)((warp_m * 32 + mt * 16 + lrow) * TSTRIDE + ks * 16 + lcol) * 2);
            u32 bfr[2][4];
#pragma unroll
            for (int p = 0; p < 2; p++)
                ldm_x4(bfr[p][0], bfr[p][1], bfr[p][2], bfr[p][3],
                       bbase + (u32)((warp_n * 32 + p * 16 + lrow) * TSTRIDE + ks * 16 + lcol) * 2);
#pragma unroll
            for (int p = 0; p < 2; p++)
#pragma unroll
                for (int q = 0; q < 2; q++) {
                    int nt2 = p * 2 + q;
#pragma unroll
                    for (int mt = 0; mt < 2; mt++)
                        mma_bf(acc[mt][nt2], af[mt], bfr[p][q], bfr[p][q + 2]);
                }
        }
    }
}

__global__ void __launch_bounds__(512, 2) fusion_k(
    const bf16* __restrict__ g16, const bf16* __restrict__ loc16,
    const bf16* __restrict__ gfT, const bf16* __restrict__ lfT,
    const bf16* __restrict__ ffT,
    const float* __restrict__ gf_b, const float* __restrict__ lf_b,
    const float* __restrict__ ff_b,
    const float* __restrict__ cx, float* __restrict__ outp)
{
    extern __shared__ bf16 smg[];
    int tid = threadIdx.x;
    int lane = tid & 31, warp = tid >> 5;
    int warp_m = warp & 3, warp_n = warp >> 2;
    int m0 = blockIdx.x << 7;
    int r = lane >> 2, c = lane & 3;
    int lrow = lane & 15;
    int lcol = (lane >> 4) << 3;

    float acc1[2][4][4], acc2[2][4][4];
#pragma unroll
    for (int i = 0; i < 2; i++)
#pragma unroll
        for (int j = 0; j < 4; j++)
#pragma unroll
            for (int q = 0; q < 4; q++) { acc1[i][j][q] = 0.f; acc2[i][j][q] = 0.f; }

    // ML1: g @ gfT ; ML2: loc @ lfT
    ml_k128(smg, g16, gfT, m0, tid, warp_m, warp_n, lrow, lcol, acc1);
    ml_k128(smg, loc16, lfT, m0, tid, warp_m, warp_n, lrow, lcol, acc2);

    __syncthreads();   // all ML2 smem reads done before t overwrites stages
    // t = relu((acc2+lf_b)*(acc1+gf_b)) -> stage A regions (k-tile = warp_n), ldmatrix layout
    {
        u32 abase = smem_u32(smg + warp_n * STG_HALFS);
#pragma unroll
        for (int mt = 0; mt < 2; mt++)
#pragma unroll
            for (int half = 0; half < 2; half++) {
                int row = warp_m * 32 + mt * 16 + r + half * 8;
#pragma unroll
                for (int nt2 = 0; nt2 < 4; nt2++) {
                    int cc = nt2 * 8 + c * 2;          // 0..31 within this k-tile
                    int col = warp_n * 32 + cc;
                    float a0 = acc1[mt][nt2][half * 2 + 0] + gf_b[col];
                    float a1 = acc1[mt][nt2][half * 2 + 1] + gf_b[col + 1];
                    float b0 = acc2[mt][nt2][half * 2 + 0] + lf_b[col];
                    float b1 = acc2[mt][nt2][half * 2 + 1] + lf_b[col + 1];
                    float t0 = a0 * b0, t1 = a1 * b1;
                    t0 = t0 > 0.f ? t0 : 0.f;
                    t1 = t1 > 0.f ? t1 : 0.f;
                    u32 pkv = bf2(t0, t1);
                    asm volatile("st.shared.b32 [%0], %1;"
                                 :: "r"(abase + (u32)(row * TSTRIDE + cc) * 2), "r"(pkv));
                }
            }
    }
    // prefetch ffT into stage B regions
    {
        int prr = tid >> 2, pcc = (tid & 3) << 3;
#pragma unroll
        for (int s = 0; s < 4; s++) {
            u32 bbase = smem_u32(smg + s * STG_HALFS) + 5120 * 2;
            cp16(bbase + (u32)(prr * TSTRIDE + pcc) * 2,
                 ffT + (size_t)prr * 128 + s * 32 + pcc);
        }
    }
    asm volatile("cp.async.commit_group;");
    asm volatile("cp.async.wait_group 0;");
    __syncthreads();

    // ML3: t @ ffT (both resident in smem)
#pragma unroll
    for (int i = 0; i < 2; i++)
#pragma unroll
        for (int j = 0; j < 4; j++)
#pragma unroll
            for (int q = 0; q < 4; q++) acc1[i][j][q] = 0.f;
#pragma unroll
    for (int t = 0; t < 4; t++) {
        u32 abase = smem_u32(smg + t * STG_HALFS);
        u32 bbase = abase + 5120 * 2;
#pragma unroll
        for (int ks = 0; ks < 2; ks++) {
            u32 af[2][4];
#pragma unroll
            for (int mt = 0; mt < 2; mt++)
                ldm_x4(af[mt][0], af[mt][1], af[mt][2], af[mt][3],
                       abase + (u32)((warp_m * 32 + mt * 16 + lrow) * TSTRIDE + ks * 16 + lcol) * 2);
            u32 bfr[2][4];
#pragma unroll
            for (int p = 0; p < 2; p++)
                ldm_x4(bfr[p][0], bfr[p][1], bfr[p][2], bfr[p][3],
                       bbase + (u32)((warp_n * 32 + p * 16 + lrow) * TSTRIDE + ks * 16 + lcol) * 2);
#pragma unroll
            for (int p = 0; p < 2; p++)
#pragma unroll
                for (int q = 0; q < 2; q++) {
                    int nt2 = p * 2 + q;
#pragma unroll
                    for (int mt = 0; mt < 2; mt++)
                        mma_bf(acc1[mt][nt2], af[mt], bfr[p][q], bfr[p][q + 2]);
                }
        }
    }

    // gate epilogue -> d_out (fp32)
#pragma unroll
    for (int mt = 0; mt < 2; mt++) {
        int row0 = m0 + warp_m * 32 + mt * 16 + r;
#pragma unroll
        for (int half = 0; half < 2; half++) {
            int row = row0 + half * 8;
#pragma unroll
            for (int nt2 = 0; nt2 < 4; nt2++) {
                int col = warp_n * 32 + nt2 * 8 + c * 2;
                float v0 = acc1[mt][nt2][half * 2 + 0] + ff_b[col];
                float v1 = acc1[mt][nt2][half * 2 + 1] + ff_b[col + 1];
                size_t off = (size_t)row * 128 + col;
                float2 e = *(const float2*)&cx[off];
                float g0 = 1.f / (1.f + expf(-v0));
                float g1 = 1.f / (1.f + expf(-v1));
                float cy0 = g0 * (e.x + tanhf(v0));
                float cy1 = g1 * (e.y + tanhf(v1));
                *(float2*)&outp[off] = make_float2(g0 * tanhf(cy0), g1 * tanhf(cy1));
            }
        }
    }
}

// ---------------- tensor-core window attention ----------------
#define ATT_STRIDE 136    // 128 d halfs + 8 pad (272 B rows)
#define ATT_SMEM   (3 * 64 * ATT_STRIDE * 2 + 900 * 4)

__global__ void __launch_bounds__(256) attn5(
    const bf16* __restrict__ qkv, const float* __restrict__ rp,
    bf16* __restrict__ out, int shift)
{
    extern __shared__ char smr[];
    bf16* qs = (bf16*)smr;
    bf16* ks = qs + 64 * ATT_STRIDE;
    bf16* vs = ks + 64 * ATT_STRIDE;
    float* rps = (float*)(vs + 64 * ATT_STRIDE);
    int tid = threadIdx.x;
    int lane = tid & 31, warp = tid >> 5;
    int bw = blockIdx.x;
    const float SCALE = 0.17677669529663687f;

    const bf16* base = qkv + (size_t)bw * 64 * 384;
#pragma unroll
    for (int i = 0; i < 12; i++) {
        int idx = tid + i * 256;
        int n = idx / 48, part = idx % 48;
        uint4 val = *(const uint4*)(base + (size_t)n * 384 + part * 8);
        bf16* dstp = (part < 16) ? qs : (part < 32) ? ks : vs;
        *(uint4*)&dstp[n * ATT_STRIDE + (part & 15) * 8] = val;
    }
    for (int i = tid; i < 900; i += 256) rps[i] = rp[i];
    __syncthreads();

    int h = warp >> 1;
    int m0 = (warp & 1) * 32;
    int cb = h * 32;
    int lrow = lane & 15;
    int lcol = (lane >> 4) << 3;

    u32 aq[2][2][4];
#pragma unroll
    for (int mt = 0; mt < 2; mt++)
#pragma unroll
        for (int kt = 0; kt < 2; kt++)
            ldm_x4(aq[mt][kt][0], aq[mt][kt][1], aq[mt][kt][2], aq[mt][kt][3],
                   smem_u32(&qs[(m0 + 16 * mt + lrow) * ATT_STRIDE + cb + 16 * kt + lcol]));

    float sacc[2][8][4];
#pragma unroll
    for (int mt = 0; mt < 2; mt++)
#pragma unroll
        for (int nt = 0; nt < 8; nt++)
#pragma unroll
            for (int q = 0; q < 4; q++) sacc[mt][nt][q] = 0.f;

#pragma unroll
    for (int ntp = 0; ntp < 4; ntp++)
#pragma unroll
        for (int kt = 0; kt < 2; kt++) {
            u32 b0, b1, b2, b3;
            ldm_x4(b0, b1, b2, b3,
                   smem_u32(&ks[(16 * ntp + lrow) * ATT_STRIDE + cb + 16 * kt + lcol]));
#pragma unroll
            for (int mt = 0; mt < 2; mt++) {
                mma_bf(sacc[mt][2 * ntp],     aq[mt][kt], b0, b2);
                mma_bf(sacc[mt][2 * ntp + 1], aq[mt][kt], b1, b3);
            }
        }

    int widx = bw & 63;
    int wh = widx >> 3, ww = widx & 7;
#pragma unroll
    for (int mt = 0; mt < 2; mt++)
#pragma unroll
        for (int q = 0; q < 4; q++) {
            int t1 = m0 + 16 * mt + (lane >> 2) + ((q >> 1) << 3);
            int r1 = t1 >> 3, s1 = t1 & 7;
            int h1 = wh * 8 + r1, w1 = ww * 8 + s1;
            int img1 = (h1 < 56 ? 0 : (h1 < 60 ? 1 : 2)) * 3 + (w1 < 56 ? 0 : (w1 < 60 ? 1 : 2));
#pragma unroll
            for (int nt = 0; nt < 8; nt++) {
                int t2 = nt * 8 + 2 * (lane & 3) + (q & 1);
                int r2 = t2 >> 3, s2 = t2 & 7;
                float v = sacc[mt][nt][q] * SCALE
                        + rps[((r1 - r2 + 7) * 15 + (s1 - s2 + 7)) * 4 + h];
                if (shift) {
                    int h2 = wh * 8 + r2, w2 = ww * 8 + s2;
                    int img2 = (h2 < 56 ? 0 : (h2 < 60 ? 1 : 2)) * 3 + (w2 < 56 ? 0 : (w2 < 60 ? 1 : 2));
                    if (img1 != img2) v -= 100.f;
                }
                sacc[mt][nt][q] = v;
            }
        }

#pragma unroll
    for (int mt = 0; mt < 2; mt++)
#pragma unroll
        for (int half = 0; half < 2; half++) {
            float mx = -1e30f;
#pragma unroll
            for (int nt = 0; nt < 8; nt++) {
                mx = fmaxf(mx, sacc[mt][nt][2 * half]);
                mx = fmaxf(mx, sacc[mt][nt][2 * half + 1]);
            }
            mx = fmaxf(mx, __shfl_xor_sync(0xffffffffu, mx, 1));
            mx = fmaxf(mx, __shfl_xor_sync(0xffffffffu, mx, 2));
            float sum = 0.f;
#pragma unroll
            for (int nt = 0; nt < 8; nt++) {
#pragma unroll
                for (int qq = 0; qq < 2; qq++) {
                    float e = __expf(sacc[mt][nt][2 * half + qq] - mx);
                    sacc[mt][nt][2 * half + qq] = e;
                    sum += e;
                }
            }
            sum += __shfl_xor_sync(0xffffffffu, sum, 1);
            sum += __shfl_xor_sync(0xffffffffu, sum, 2);
            float inv = 1.f / sum;
#pragma unroll
            for (int nt = 0; nt < 8; nt++) {
                sacc[mt][nt][2 * half] *= inv;
                sacc[mt][nt][2 * half + 1] *= inv;
            }
        }

    u32 pa[2][4][4];
#pragma unroll
    for (int mt = 0; mt < 2; mt++)
#pragma unroll
        for (int j = 0; j < 4; j++) {
            pa[mt][j][0] = bf2(sacc[mt][2 * j][0],     sacc[mt][2 * j][1]);
            pa[mt][j][1] = bf2(sacc[mt][2 * j][2],     sacc[mt][2 * j][3]);
            pa[mt][j][2] = bf2(sacc[mt][2 * j + 1][0], sacc[mt][2 * j + 1][1]);
            pa[mt][j][3] = bf2(sacc[mt][2 * j + 1][2], sacc[mt][2 * j + 1][3]);
        }

    float oacc[2][4][4];
#pragma unroll
    for (int mt = 0; mt < 2; mt++)
#pragma unroll
        for (int nt2 = 0; nt2 < 4; nt2++)
#pragma unroll
            for (int q = 0; q < 4; q++) oacc[mt][nt2][q] = 0.f;

#pragma unroll
    for (int j = 0; j < 4; j++)
#pragma unroll
        for (int ntp = 0; ntp < 2; ntp++) {
            u32 b0, b1, b2, b3;
            ldmt_x4(b0, b1, b2, b3,
                    smem_u32(&vs[(16 * j + lrow) * ATT_STRIDE + cb + 16 * ntp + lcol]));
#pragma unroll
            for (int mt = 0; mt < 2; mt++) {
                mma_bf(oacc[mt][2 * ntp],     pa[mt][j], b0, b1);
                mma_bf(oacc[mt][2 * ntp + 1], pa[mt][j], b2, b3);
            }
        }

#pragma unroll
    for (int mt = 0; mt < 2; mt++) {
        int row0 = bw * 64 + m0 + 16 * mt + (lane >> 2);
        int col  = cb + 2 * (lane & 3);
#pragma unroll
        for (int nt2 = 0; nt2 < 4; nt2++) {
            *(u32*)&out[(size_t)row0 * 128 + col + nt2 * 8]       = bf2(oacc[mt][nt2][0], oacc[mt][nt2][1]);
            *(u32*)&out[(size_t)(row0 + 8) * 128 + col + nt2 * 8] = bf2(oacc[mt][nt2][2], oacc[mt][nt2][3]);
        }
    }
}

// ---------------- fused deformable-conv branch (offset/mask conv + gather) ----------------
__global__ void __launch_bounds__(256) local_k(
    const float* __restrict__ xt,
    const float* __restrict__ ow, const float* __restrict__ ob,
    const float* __restrict__ mw, const float* __restrict__ mb,
    bf16* __restrict__ outp)
{
    __shared__ float rows[34][128];
    __shared__ float wo_s[1152], wm_s[1152];
    __shared__ int   s_fp[3][32];
    __shared__ float s_a0[3][32], s_a1[3][32];
    __shared__ bf16  smout[32][130];
    int b  = blockIdx.x >> 7;
    int l0 = (blockIdx.x & 127) << 5;
    int tid = threadIdx.x;
    int warp = tid >> 5, lane = tid & 31;

    for (int i = tid; i < 1152; i += 256) { wo_s[i] = ow[i]; wm_s[i] = mw[i]; }
#pragma unroll
    for (int i = 0; i < 5; i++) {
        int idx = i * 256 + tid;             // float4 ids, need 34*32 = 1088
        if (idx < 1088) {
            int rr = idx >> 5, c4 = (idx & 31) << 2;
            int l = l0 - 1 + rr;
            if (l >= 0 && l < 4096)
                *(float4*)&rows[rr][c4] = *(const float4*)(xt + ((size_t)b * 4096 + l) * 128 + c4);
        }
    }
    __syncthreads();

    int c0 = lane << 2;
#pragma unroll
    for (int it = 0; it < 4; it++) {
        int tl = warp * 4 + it;              // local token 0..31
        int l = l0 + tl;
        float so[3] = {0.f, 0.f, 0.f}, sm[3] = {0.f, 0.f, 0.f};
#pragma unroll
        for (int j = 0; j < 3; j++) {
            int ll = l + j - 1;
            if (ll < 0 || ll > 4095) continue;
            float4 xv = *(const float4*)&rows[tl + j][c0];
#pragma unroll
            for (int k = 0; k < 3; k++) {
                const float* owp = wo_s + k * 384 + j;
                const float* mwp = wm_s + k * 384 + j;
                so[k] += xv.x * owp[(c0 + 0) * 3] + xv.y * owp[(c0 + 1) * 3]
                       + xv.z * owp[(c0 + 2) * 3] + xv.w * owp[(c0 + 3) * 3];
                sm[k] += xv.x * mwp[(c0 + 0) * 3] + xv.y * mwp[(c0 + 1) * 3]
                       + xv.z * mwp[(c0 + 2) * 3] + xv.w * mwp[(c0 + 3) * 3];
            }
        }
#pragma unroll
        for (int o = 16; o > 0; o >>= 1) {
#pragma unroll
            for (int k = 0; k < 3; k++) {
                so[k] += __shfl_xor_sync(0xffffffffu, so[k], o);
                sm[k] += __shfl_xor_sync(0xffffffffu, sm[k], o);
            }
        }
        if (lane < 3) {
            int k = lane;
            float off = ob[k] + so[k];
            float mk  = mb[k] + sm[k];
            float mask = 1.f / (1.f + expf(-mk));
            float pos = fminf(fmaxf((float)l + off, 0.f), 4095.f);
            float fpf = floorf(pos);
            int f = (int)fpf;
            float alpha = pos - fpf;
            s_fp[k][tl] = f;
            s_a0[k][tl] = (1.f - alpha) * mask;
            s_a1[k][tl] = alpha * mask;
        }
    }
    __syncthreads();

    // phase 2: gather + bf16, transpose via smem, coalesced (B,C,L) write
#pragma unroll
    for (int i = 0; i < 16; i++) {
        int idx = i * 256 + tid;          // 0..4095
        int dl = idx >> 7, c = idx & 127;
        float o = 0.f;
#pragma unroll
        for (int k = 0; k < 3; k++) {
            int f  = s_fp[k][dl];
            int cp = min(f + 1, 4095);
            o += xt[((size_t)b * 4096 + f)  * 128 + c] * s_a0[k][dl]
               + xt[((size_t)b * 4096 + cp) * 128 + c] * s_a1[k][dl];
        }
        smout[dl][c] = __float2bfloat16_rn(o);
    }
    __syncthreads();
#pragma unroll
    for (int i = 0; i < 16; i++) {
        int idx = i * 256 + tid;
        int c = idx >> 5, dl = idx & 31;
        outp[(size_t)b * 524288 + (size_t)c * 4096 + l0 + dl] = smout[dl][c];
    }
}

// ---------------- host launcher ----------------
extern "C" void kernel_launch(void* const* d_in, const int* in_sizes, int n_in,
                              void* d_out, int out_size)
{
    const float* xt    = (const float*)d_in[0];
    const float* hx    = (const float*)d_in[1];
    const float* cx    = (const float*)d_in[2];
    const float* red_w = (const float*)d_in[3];
    const float* red_b = (const float*)d_in[4];
    const float* n1g   = (const float*)d_in[5];
    const float* n1b   = (const float*)d_in[6];
    const float* qkvw  = (const float*)d_in[7];
    const float* qkvb  = (const float*)d_in[8];
    const float* rp    = (const float*)d_in[9];
    const float* pw    = (const float*)d_in[10];
    const float* pb    = (const float*)d_in[11];
    const float* n2g   = (const float*)d_in[12];
    const float* n2b   = (const float*)d_in[13];
    const float* f1w   = (const float*)d_in[14];
    const float* f1b   = (const float*)d_in[15];
    const float* f2w   = (const float*)d_in[16];
    const float* f2b   = (const float*)d_in[17];
    const float* off_w = (const float*)d_in[18];
    const float* off_b = (const float*)d_in[19];
    const float* msk_w = (const float*)d_in[20];
    const float* msk_b = (const float*)d_in[21];
    const float* lf_w  = (const float*)d_in[22];
    const float* lf_b  = (const float*)d_in[23];
    const float* gf_w  = (const float*)d_in[24];
    const float* gf_b  = (const float*)d_in[25];
    const float* ff_w  = (const float*)d_in[26];
    const float* ff_b  = (const float*)d_in[27];

    float* px;
    bf16 *pbig16, *pxw16, *patt16, *ploc16, *px16;
    bf16 *predT, *pqkvT, *ppwT, *pf1T, *pf2T, *plfT, *pgfT, *pffT;
    cudaGetSymbolAddress((void**)&px,    d_x);
    cudaGetSymbolAddress((void**)&pbig16, g_big16);
    cudaGetSymbolAddress((void**)&pxw16, g_xw16);
    cudaGetSymbolAddress((void**)&patt16, g_att16);
    cudaGetSymbolAddress((void**)&ploc16, g_loc16);
    cudaGetSymbolAddress((void**)&px16,  g_x16);
    cudaGetSymbolAddress((void**)&predT, g_redT);
    cudaGetSymbolAddress((void**)&pqkvT, g_qkvT);
    cudaGetSymbolAddress((void**)&ppwT,  g_pwT);
    cudaGetSymbolAddress((void**)&pf1T,  g_f1T);
    cudaGetSymbolAddress((void**)&pf2T,  g_f2T);
    cudaGetSymbolAddress((void**)&plfT,  g_lfT);
    cudaGetSymbolAddress((void**)&pgfT,  g_gfT);
    cudaGetSymbolAddress((void**)&pffT,  g_ffT);

    cudaFuncSetAttribute(gemm_tc<M_CONCAT_LN,128,256>,  cudaFuncAttributeMaxDynamicSharedMemorySize, GEMM_SMEM);
    cudaFuncSetAttribute(gemm_tc<M_PLAIN,384,128>,      cudaFuncAttributeMaxDynamicSharedMemorySize, GEMM_SMEM);
    cudaFuncSetAttribute(gemm_tc<M_PERMRES_LN,128,128>, cudaFuncAttributeMaxDynamicSharedMemorySize, GEMM_SMEM);
    cudaFuncSetAttribute(gemm_tc<M_GELU,512,128>,       cudaFuncAttributeMaxDynamicSharedMemorySize, GEMM_SMEM);
    cudaFuncSetAttribute(gemm_tc<M_RES_LN,128,512>,     cudaFuncAttributeMaxDynamicSharedMemorySize, GEMM_SMEM);
    cudaFuncSetAttribute(gemm_tc<M_RES,128,512>,        cudaFuncAttributeMaxDynamicSharedMemorySize, GEMM_SMEM);
    cudaFuncSetAttribute(fusion_k,                      cudaFuncAttributeMaxDynamicSharedMemorySize, GEMM_SMEM);
    cudaFuncSetAttribute(attn5,                         cudaFuncAttributeMaxDynamicSharedMemorySize, ATT_SMEM);

    // weight transpose-convert (fp32 KxN -> bf16 NxK)
    WPack wp;
    wp.e[0]  = { red_w,           predT,           256, 128 };
    wp.e[1]  = { qkvw,            pqkvT,           128, 384 };
    wp.e[2]  = { qkvw + 49152,    pqkvT + 49152,   128, 384 };
    wp.e[3]  = { pw,              ppwT,            128, 128 };
    wp.e[4]  = { pw + 16384,      ppwT + 16384,    128, 128 };
    wp.e[5]  = { f1w,             pf1T,            128, 512 };
    wp.e[6]  = { f1w + 65536,     pf1T + 65536,    128, 512 };
    wp.e[7]  = { f2w,             pf2T,            512, 128 };
    wp.e[8]  = { f2w + 65536,     pf2T + 65536,    512, 128 };
    wp.e[9]  = { lf_w,            plfT,            128, 128 };
    wp.e[10] = { gf_w,            pgfT,            128, 128 };
    wp.e[11] = { ff_w,            pffT,            128, 128 };
    wconv_k<<<dim3(48, 12), 256>>>(wp);

    // local (deformable) branch — fused offsets + gather
    local_k<<<Bn * 128, 256>>>(xt, off_w, off_b, msk_w, msk_b, ploc16);

    // global branch: reduce GEMM with fused concat input + fused LN1(block0, shift 0)
    gemm_tc<M_CONCAT_LN,128,256><<<dim3(1, 256), 512, GEMM_SMEM>>>(
        nullptr, predT, red_b, nullptr, px, pxw16, n1g, n1b, 0, xt, hx);

    for (int i = 0; i < 2; i++) {
        int shift = i ? 4 : 0;
        gemm_tc<M_PLAIN,384,128><<<dim3(3, 256), 512, GEMM_SMEM>>>(
            pxw16, pqkvT + i * 49152, qkvb + i * 384, nullptr,
            nullptr, pbig16, nullptr, nullptr, 0, nullptr, nullptr);
        attn5<<<512, 256, ATT_SMEM>>>(pbig16, rp + i * 900, patt16, shift);
        gemm_tc<M_PERMRES_LN,128,128><<<dim3(1, 256), 512, GEMM_SMEM>>>(
            patt16, ppwT + i * 16384, pb + i * 128, px,
            px, pxw16, n2g + i * 128, n2b + i * 128, shift, nullptr, nullptr);
        gemm_tc<M_GELU,512,128><<<dim3(4, 256), 512, GEMM_SMEM>>>(
            pxw16, pf1T + i * 65536, f1b + i * 512, nullptr,
            nullptr, pbig16, nullptr, nullptr, 0, nullptr, nullptr);
        if (i == 0) {
            gemm_tc<M_RES_LN,128,512><<<dim3(1, 256), 512, GEMM_SMEM>>>(
                pbig16, pf2T, f2b, px,
                px, pxw16, n1g + 128, n1b + 128, 4, nullptr, nullptr);
        } else {
            gemm_tc<M_RES,128,512><<<dim3(1, 256), 512, GEMM_SMEM>>>(
                pbig16, pf2T + 65536, f2b + 128, px,
                px, px16, nullptr, nullptr, 0, nullptr, nullptr);
        }
    }

    // fused fusion + LSTM gate
    fusion_k<<<256, 512, GEMM_SMEM>>>(px16, ploc16, pgfT, plfT, pffT,
                                      gf_b, lf_b, ff_b, cx, (float*)d_out);
}

// round 15
// speedup vs baseline: 1.5664x; 1.0125x over previous
#include <cuda_runtime.h>
#include <cuda_bf16.h>
#include <math.h>

// Problem constants
#define Bn   8
#define Ln   4096
#define Cn   128
#define BL   32768            // B*L rows

typedef unsigned int u32;
typedef unsigned long long u64;
typedef __nv_bfloat16 bf16;

// ---------------- helpers ----------------
__device__ __forceinline__ u32 smem_u32(const void* p) {
    u32 a;
    asm("{ .reg .u64 t; cvta.to.shared.u64 t, %1; cvt.u32.u64 %0, t; }" : "=r"(a) : "l"(p));
    return a;
}
__device__ __forceinline__ void cp16(u32 dst, const void* src) {
    size_t g = __cvta_generic_to_global(src);
    asm volatile("cp.async.cg.shared.global [%0], [%1], 16;" :: "r"(dst), "l"(g));
}
__device__ __forceinline__ void ldm_x4(u32& r0, u32& r1, u32& r2, u32& r3, u32 addr) {
    asm volatile("ldmatrix.sync.aligned.m8n8.x4.shared.b16 {%0,%1,%2,%3}, [%4];"
                 : "=r"(r0), "=r"(r1), "=r"(r2), "=r"(r3) : "r"(addr));
}
__device__ __forceinline__ void ldmt_x4(u32& r0, u32& r1, u32& r2, u32& r3, u32 addr) {
    asm volatile("ldmatrix.sync.aligned.m8n8.x4.trans.shared.b16 {%0,%1,%2,%3}, [%4];"
                 : "=r"(r0), "=r"(r1), "=r"(r2), "=r"(r3) : "r"(addr));
}
__device__ __forceinline__ u32 bf2(float a, float b) {
    __nv_bfloat162 h;
    h.x = __float2bfloat16_rn(a);
    h.y = __float2bfloat16_rn(b);
    return *(u32*)&h;
}
__device__ __forceinline__ void mma_bf(float* c, const u32* a, u32 b0, u32 b1) {
    asm volatile(
        "mma.sync.aligned.m16n8k16.row.col.f32.bf16.bf16.f32 "
        "{%0,%1,%2,%3},{%4,%5,%6,%7},{%8,%9},{%0,%1,%2,%3};"
        : "+f"(c[0]), "+f"(c[1]), "+f"(c[2]), "+f"(c[3])
        : "r"(a[0]), "r"(a[1]), "r"(a[2]), "r"(a[3]), "r"(b0), "r"(b1));
}

// ---------------- scratch (device globals; no allocs allowed) ----------------
__device__ float d_x   [BL * Cn];      // running stream (fp32)
__device__ bf16  g_big16[BL * 512];    // qkv / MLP hidden (bf16)
__device__ bf16  g_xw16 [BL * Cn];     // LN output (bf16)
__device__ bf16  g_att16[BL * Cn];     // attention out (bf16)
__device__ bf16  g_loc16[BL * Cn];     // deform out (bf16, (B,C,L) flat)
__device__ bf16  g_x16  [BL * Cn];     // final g (bf16)
// transposed bf16 weights (N x K row-major)
__device__ bf16  g_redT[128 * 256];
__device__ bf16  g_qkvT[2 * 384 * 128];
__device__ bf16  g_pwT [2 * 128 * 128];
__device__ bf16  g_f1T [2 * 512 * 128];
__device__ bf16  g_f2T [2 * 128 * 512];
__device__ bf16  g_lfT [128 * 128];
__device__ bf16  g_gfT [128 * 128];
__device__ bf16  g_ffT [128 * 128];

// window-layout row m  ->  token index (b*L + ho*64 + wo)
__device__ __forceinline__ int win_to_token(int m, int shift) {
    int n    = m & 63;
    int bw   = m >> 6;
    int widx = bw & 63;
    int b    = bw >> 6;
    int wh = widx >> 3, ww = widx & 7;
    int r = n >> 3, s = n & 7;
    int ho = (wh * 8 + r + shift) & 63;
    int wo = (ww * 8 + s + shift) & 63;
    return (b << 12) + (ho << 6) + wo;
}
// token index -> window-layout row (exact inverse)
__device__ __forceinline__ int token_to_win(int t, int shift) {
    int b = t >> 12, rem = t & 4095;
    int ho = rem >> 6, wo = rem & 63;
    int u = (ho - shift) & 63, v = (wo - shift) & 63;
    int wh = u >> 3, r = u & 7;
    int ww = v >> 3, s = v & 7;
    return (((b << 6) + (wh << 3) + ww) << 6) + (r << 3) + s;
}

// ---------------- weight transpose-convert: (K x N fp32) -> (N x K bf16) ----------------
struct WEnt { const float* src; bf16* dst; int K; int N; };
struct WPack { WEnt e[12]; };

__global__ void __launch_bounds__(256) wconv_k(WPack p) {
    WEnt w = p.e[blockIdx.y];
    int total = w.K * w.N;
    for (int i = blockIdx.x * 256 + threadIdx.x; i < total; i += gridDim.x * 256) {
        int n = i / w.K, k = i - n * w.K;
        w.dst[i] = __float2bfloat16_rn(w.src[(size_t)k * w.N + n]);
    }
}

// ---------------- bf16 tensor-core GEMM: 128x128 tile, 16 warps (32x32/warp) ---------------
// K,N compile-time. K==128: all 4 k-tiles resident, ONE barrier. K>128: 4-stage pipeline.
enum { M_PLAIN = 0, M_GELU, M_RES, M_PERMRES,
       M_PLAIN_LN, M_RES_LN, M_PERMRES_LN, M_CONCAT_LN };

#define TSTRIDE 40            // 32 k halfs + 8 pad (80 B rows)
#define STG_HALFS 10240       // per stage: A 5120 halfs + B 5120 halfs (20480 B)
#define GEMM_SMEM (4 * STG_HALFS * 2)   // 81920 B

template <int MODE, int NN, int KK>
__global__ void __launch_bounds__(512, 2) gemm_tc(
    const bf16* __restrict__ A, const bf16* __restrict__ BT,
    const float* __restrict__ bias, const float* __restrict__ extra,
    float* __restrict__ C, bf16* __restrict__ C16,
    const float* __restrict__ lng, const float* __restrict__ lnb,
    int shift,
    const float* __restrict__ Ax, const float* __restrict__ Ah)
{
    extern __shared__ bf16 smg[];
    int tid = threadIdx.x;
    int lane = tid & 31, warp = tid >> 5;       // warp 0..15
    int warp_m = warp & 3, warp_n = warp >> 2;  // 4 (M) x 4 (N), 32x32 tiles
    int m0 = blockIdx.y << 7, n0 = blockIdx.x << 7;
    int r = lane >> 2, c = lane & 3;

    const bool LN = (MODE == M_PLAIN_LN || MODE == M_RES_LN ||
                     MODE == M_PERMRES_LN || MODE == M_CONCAT_LN);

    float acc[2][4][4];
#pragma unroll
    for (int i = 0; i < 2; i++)
#pragma unroll
        for (int j = 0; j < 4; j++)
#pragma unroll
            for (int q = 0; q < 4; q++) acc[i][j][q] = 0.f;

    const int prr = tid >> 2;                    // 0..127
    const int pcc = (tid & 3) << 3;              // 0,8,16,24
    auto prefetch = [&](int k0, int s) {
        u32 abase = smem_u32(smg + s * STG_HALFS);
        u32 bbase = abase + 5120 * 2;
        if (MODE == M_CONCAT_LN) {
            // fused concat(xt,hx) -> bf16 staging (fp32 LDG + cvt + STS)
            int gk = k0 + pcc;
            const float* srcp = (gk < 128) ? Ax + (size_t)(m0 + prr) * 128 + gk
                                           : Ah + (size_t)(m0 + prr) * 128 + gk - 128;
            float4 v0 = *(const float4*)srcp;
            float4 v1 = *(const float4*)(srcp + 4);
            u32 w0 = bf2(v0.x, v0.y), w1 = bf2(v0.z, v0.w);
            u32 w2 = bf2(v1.x, v1.y), w3 = bf2(v1.z, v1.w);
            asm volatile("st.shared.v4.b32 [%0], {%1,%2,%3,%4};"
                         :: "r"(abase + (u32)(prr * TSTRIDE + pcc) * 2),
                            "r"(w0), "r"(w1), "r"(w2), "r"(w3));
        } else {
            cp16(abase + (u32)(prr * TSTRIDE + pcc) * 2,
                 A + (size_t)(m0 + prr) * KK + k0 + pcc);
        }
        cp16(bbase + (u32)(prr * TSTRIDE + pcc) * 2,
             BT + (size_t)(n0 + prr) * KK + k0 + pcc);
        asm volatile("cp.async.commit_group;");
    };

    int lrow = lane & 15;
    int lcol = (lane >> 4) << 3;                 // 0 or 8 halfs

    constexpr int ntk = KK >> 5;

    auto mma_tile = [&](int t) {
        u32 abase = smem_u32(smg + (t & 3) * STG_HALFS);
        u32 bbase = abase + 5120 * 2;
#pragma unroll
        for (int ks = 0; ks < 2; ks++) {
            u32 af[2][4];
#pragma unroll
            for (int mt = 0; mt < 2; mt++)
                ldm_x4(af[mt][0], af[mt][1], af[mt][2], af[mt][3],
                       abase + (u32)((warp_m * 32 + mt * 16 + lrow) * TSTRIDE + ks * 16 + lcol) * 2);
            u32 bfr[2][4];
#pragma unroll
            for (int p = 0; p < 2; p++)
                ldm_x4(bfr[p][0], bfr[p][1], bfr[p][2], bfr[p][3],
                       bbase + (u32)((warp_n * 32 + p * 16 + lrow) * TSTRIDE + ks * 16 + lcol) * 2);
#pragma unroll
            for (int p = 0; p < 2; p++)
#pragma unroll
                for (int q = 0; q < 2; q++) {
                    int nt2 = p * 2 + q;
                    u32 b0 = bfr[p][q], b1 = bfr[p][q + 2];
#pragma unroll
                    for (int mt = 0; mt < 2; mt++)
                        mma_bf(acc[mt][nt2], af[mt], b0, b1);
                }
        }
    };

    if (KK == 128) {
        // all 4 k-tiles resident: one wait, one barrier, uninterrupted MMA stream
        prefetch(0, 0); prefetch(32, 1); prefetch(64, 2); prefetch(96, 3);
        asm volatile("cp.async.wait_group 0;");
        __syncthreads();
#pragma unroll
        for (int t = 0; t < 4; t++) mma_tile(t);
    } else {
        prefetch(0, 0);
        if (ntk > 1) prefetch(32, 1);
#pragma unroll
        for (int t = 0; t < ntk; t++) {
            if (t + 2 < ntk) prefetch((t + 2) << 5, (t + 2) & 3);
            if (t < ntk - 2)       asm volatile("cp.async.wait_group 2;");
            else if (t == ntk - 2) asm volatile("cp.async.wait_group 1;");
            else                   asm volatile("cp.async.wait_group 0;");
            __syncthreads();
            mma_tile(t);
        }
    }

    if (!LN) {
#pragma unroll
        for (int mt = 0; mt < 2; mt++) {
            int row0 = m0 + warp_m * 32 + mt * 16 + r;
#pragma unroll
            for (int half = 0; half < 2; half++) {
                int row = row0 + half * 8;
                int dst = (MODE == M_PERMRES) ? win_to_token(row, shift) : row;
#pragma unroll
                for (int nt2 = 0; nt2 < 4; nt2++) {
                    int col = n0 + warp_n * 32 + nt2 * 8 + c * 2;
                    float v0 = acc[mt][nt2][half * 2 + 0] + bias[col];
                    float v1 = acc[mt][nt2][half * 2 + 1] + bias[col + 1];
                    size_t off = (size_t)dst * NN + col;
                    if (MODE == M_GELU) {
                        v0 = 0.5f * v0 * (1.f + erff(v0 * 0.70710678118654752f));
                        v1 = 0.5f * v1 * (1.f + erff(v1 * 0.70710678118654752f));
                    } else if (MODE == M_RES || MODE == M_PERMRES) {
                        float2 e = *(const float2*)&extra[off];
                        v0 += e.x; v1 += e.y;
                    }
                    if (C)   *(float2*)&C[off] = make_float2(v0, v1);
                    if (C16) *(u32*)&C16[off]  = bf2(v0, v1);
                }
            }
        }
        return;
    }

    // ---- fused-LN epilogue (NN == 128) ----
    float rsum[2][2], rsq[2][2];
#pragma unroll
    for (int mt = 0; mt < 2; mt++) {
        int row0 = m0 + warp_m * 32 + mt * 16 + r;
#pragma unroll
        for (int half = 0; half < 2; half++) {
            int row = row0 + half * 8;
            int dst = (MODE == M_PERMRES_LN) ? win_to_token(row, shift) : row;
            float s = 0.f, sq = 0.f;
#pragma unroll
            for (int nt2 = 0; nt2 < 4; nt2++) {
                int col = n0 + warp_n * 32 + nt2 * 8 + c * 2;
                float v0 = acc[mt][nt2][half * 2 + 0] + bias[col];
                float v1 = acc[mt][nt2][half * 2 + 1] + bias[col + 1];
                if (MODE == M_RES_LN || MODE == M_PERMRES_LN) {
                    float2 e = *(const float2*)&extra[(size_t)dst * 128 + col];
                    v0 += e.x; v1 += e.y;
                }
                acc[mt][nt2][half * 2 + 0] = v0;
                acc[mt][nt2][half * 2 + 1] = v1;
                s += v0 + v1; sq += v0 * v0 + v1 * v1;
            }
            s  += __shfl_xor_sync(0xffffffffu, s, 1);
            s  += __shfl_xor_sync(0xffffffffu, s, 2);
            sq += __shfl_xor_sync(0xffffffffu, sq, 1);
            sq += __shfl_xor_sync(0xffffffffu, sq, 2);
            rsum[mt][half] = s; rsq[mt][half] = sq;
        }
    }
    __syncthreads();
    float* part = (float*)smg;             // [128 rows][4 warp_n][2]
    if ((lane & 3) == 0) {
#pragma unroll
        for (int mt = 0; mt < 2; mt++)
#pragma unroll
            for (int half = 0; half < 2; half++) {
                int rowloc = warp_m * 32 + mt * 16 + (lane >> 2) + half * 8;
                part[rowloc * 8 + warp_n * 2 + 0] = rsum[mt][half];
                part[rowloc * 8 + warp_n * 2 + 1] = rsq[mt][half];
            }
    }
    __syncthreads();
#pragma unroll
    for (int mt = 0; mt < 2; mt++) {
#pragma unroll
        for (int half = 0; half < 2; half++) {
            int rowloc = warp_m * 32 + mt * 16 + r + half * 8;
            float s  = part[rowloc * 8] + part[rowloc * 8 + 2]
                     + part[rowloc * 8 + 4] + part[rowloc * 8 + 6];
            float sq = part[rowloc * 8 + 1] + part[rowloc * 8 + 3]
                     + part[rowloc * 8 + 5] + part[rowloc * 8 + 7];
            float mu = s * 0.0078125f;
            float var = sq * 0.0078125f - mu * mu;
            float rstd = rsqrtf(var + 1e-5f);
            int row = m0 + rowloc;
            int xdst, wdst;
            if (MODE == M_PERMRES_LN) { xdst = win_to_token(row, shift); wdst = xdst; }
            else                      { xdst = row; wdst = token_to_win(row, shift); }
#pragma unroll
            for (int nt2 = 0; nt2 < 4; nt2++) {
                int col = n0 + warp_n * 32 + nt2 * 8 + c * 2;
                float v0 = acc[mt][nt2][half * 2 + 0];
                float v1 = acc[mt][nt2][half * 2 + 1];
                *(float2*)&C[(size_t)xdst * 128 + col] = make_float2(v0, v1);
                float w0 = (v0 - mu) * rstd * lng[col]     + lnb[col];
                float w1 = (v1 - mu) * rstd * lng[col + 1] + lnb[col + 1];
                *(u32*)&C16[(size_t)wdst * 128 + col] = bf2(w0, w1);
            }
        }
    }
}

// ---------------- fused fusion + LSTM gate kernel (16 warps, 32x32 tiles) ----------------
__device__ __forceinline__ void ml_k128(
    bf16* smg, const bf16* A, const bf16* BT, int m0,
    int tid, int warp_m, int warp_n, int lrow, int lcol,
    float (&acc)[2][4][4])
{
    __syncthreads();   // previous smem users done
    int prr = tid >> 2, pcc = (tid & 3) << 3;
#pragma unroll
    for (int s = 0; s < 4; s++) {
        u32 abase = smem_u32(smg + s * STG_HALFS);
        u32 bbase = abase + 5120 * 2;
        cp16(abase + (u32)(prr * TSTRIDE + pcc) * 2,
             A + (size_t)(m0 + prr) * 128 + s * 32 + pcc);
        cp16(bbase + (u32)(prr * TSTRIDE + pcc) * 2,
             BT + (size_t)prr * 128 + s * 32 + pcc);
    }
    asm volatile("cp.async.commit_group;");
    asm volatile("cp.async.wait_group 0;");
    __syncthreads();
#pragma unroll
    for (int t = 0; t < 4; t++) {
        u32 abase = smem_u32(smg + t * STG_HALFS);
        u32 bbase = abase + 5120 * 2;
#pragma unroll
        for (int ks = 0; ks < 2; ks++) {
            u32 af[2][4];
#pragma unroll
            for (int mt = 0; mt < 2; mt++)
                ldm_x4(af[mt][0], af[mt][1], af[mt][2], af[mt][3],
                       abase + (u32)((warp_m * 32 + mt * 16 + lrow) * TSTRIDE + ks * 16 + lcol) * 2);
            u32 bfr[2][4];
#pragma unroll
            for (int p = 0; p < 2; p++)
                ldm_x4(bfr[p][0], bfr[p][1], bfr[p][2], bfr[p][3],
                       bbase + (u32)((warp_n * 32 + p * 16 + lrow) * TSTRIDE + ks * 16 + lcol) * 2);
#pragma unroll
            for (int p = 0; p < 2; p++)
#pragma unroll
                for (int q = 0; q < 2; q++) {
                    int nt2 = p * 2 + q;
#pragma unroll
                    for (int mt = 0; mt < 2; mt++)
                        mma_bf(acc[mt][nt2], af[mt], bfr[p][q], bfr[p][q + 2]);
                }
        }
    }
}

__global__ void __launch_bounds__(512, 2) fusion_k(
    const bf16* __restrict__ g16, const bf16* __restrict__ loc16,
    const bf16* __restrict__ gfT, const bf16* __restrict__ lfT,
    const bf16* __restrict__ ffT,
    const float* __restrict__ gf_b, const float* __restrict__ lf_b,
    const float* __restrict__ ff_b,
    const float* __restrict__ cx, float* __restrict__ outp)
{
    extern __shared__ bf16 smg[];
    int tid = threadIdx.x;
    int lane = tid & 31, warp = tid >> 5;
    int warp_m = warp & 3, warp_n = warp >> 2;
    int m0 = blockIdx.x << 7;
    int r = lane >> 2, c = lane & 3;
    int lrow = lane & 15;
    int lcol = (lane >> 4) << 3;

    float acc1[2][4][4], acc2[2][4][4];
#pragma unroll
    for (int i = 0; i < 2; i++)
#pragma unroll
        for (int j = 0; j < 4; j++)
#pragma unroll
            for (int q = 0; q < 4; q++) { acc1[i][j][q] = 0.f; acc2[i][j][q] = 0.f; }

    // ML1: g @ gfT ; ML2: loc @ lfT
    ml_k128(smg, g16, gfT, m0, tid, warp_m, warp_n, lrow, lcol, acc1);
    ml_k128(smg, loc16, lfT, m0, tid, warp_m, warp_n, lrow, lcol, acc2);

    __syncthreads();   // all ML2 smem reads done before t overwrites stages
    // t = relu((acc2+lf_b)*(acc1+gf_b)) -> stage A regions (k-tile = warp_n), ldmatrix layout
    {
        u32 abase = smem_u32(smg + warp_n * STG_HALFS);
#pragma unroll
        for (int mt = 0; mt < 2; mt++)
#pragma unroll
            for (int half = 0; half < 2; half++) {
                int row = warp_m * 32 + mt * 16 + r + half * 8;
#pragma unroll
                for (int nt2 = 0; nt2 < 4; nt2++) {
                    int cc = nt2 * 8 + c * 2;          // 0..31 within this k-tile
                    int col = warp_n * 32 + cc;
                    float a0 = acc1[mt][nt2][half * 2 + 0] + gf_b[col];
                    float a1 = acc1[mt][nt2][half * 2 + 1] + gf_b[col + 1];
                    float b0 = acc2[mt][nt2][half * 2 + 0] + lf_b[col];
                    float b1 = acc2[mt][nt2][half * 2 + 1] + lf_b[col + 1];
                    float t0 = a0 * b0, t1 = a1 * b1;
                    t0 = t0 > 0.f ? t0 : 0.f;
                    t1 = t1 > 0.f ? t1 : 0.f;
                    u32 pkv = bf2(t0, t1);
                    asm volatile("st.shared.b32 [%0], %1;"
                                 :: "r"(abase + (u32)(row * TSTRIDE + cc) * 2), "r"(pkv));
                }
            }
    }
    // prefetch ffT into stage B regions
    {
        int prr = tid >> 2, pcc = (tid & 3) << 3;
#pragma unroll
        for (int s = 0; s < 4; s++) {
            u32 bbase = smem_u32(smg + s * STG_HALFS) + 5120 * 2;
            cp16(bbase + (u32)(prr * TSTRIDE + pcc) * 2,
                 ffT + (size_t)prr * 128 + s * 32 + pcc);
        }
    }
    asm volatile("cp.async.commit_group;");
    asm volatile("cp.async.wait_group 0;");
    __syncthreads();

    // ML3: t @ ffT (both resident in smem)
#pragma unroll
    for (int i = 0; i < 2; i++)
#pragma unroll
        for (int j = 0; j < 4; j++)
#pragma unroll
            for (int q = 0; q < 4; q++) acc1[i][j][q] = 0.f;
#pragma unroll
    for (int t = 0; t < 4; t++) {
        u32 abase = smem_u32(smg + t * STG_HALFS);
        u32 bbase = abase + 5120 * 2;
#pragma unroll
        for (int ks = 0; ks < 2; ks++) {
            u32 af[2][4];
#pragma unroll
            for (int mt = 0; mt < 2; mt++)
                ldm_x4(af[mt][0], af[mt][1], af[mt][2], af[mt][3],
                       abase + (u32)((warp_m * 32 + mt * 16 + lrow) * TSTRIDE + ks * 16 + lcol) * 2);
            u32 bfr[2][4];
#pragma unroll
            for (int p = 0; p < 2; p++)
                ldm_x4(bfr[p][0], bfr[p][1], bfr[p][2], bfr[p][3],
                       bbase + (u32)((warp_n * 32 + p * 16 + lrow) * TSTRIDE + ks * 16 + lcol) * 2);
#pragma unroll
            for (int p = 0; p < 2; p++)
#pragma unroll
                for (int q = 0; q < 2; q++) {
                    int nt2 = p * 2 + q;
#pragma unroll
                    for (int mt = 0; mt < 2; mt++)
                        mma_bf(acc1[mt][nt2], af[mt], bfr[p][q], bfr[p][q + 2]);
                }
        }
    }

    // gate epilogue -> d_out (fp32)
#pragma unroll
    for (int mt = 0; mt < 2; mt++) {
        int row0 = m0 + warp_m * 32 + mt * 16 + r;
#pragma unroll
        for (int half = 0; half < 2; half++) {
            int row = row0 + half * 8;
#pragma unroll
            for (int nt2 = 0; nt2 < 4; nt2++) {
                int col = warp_n * 32 + nt2 * 8 + c * 2;
                float v0 = acc1[mt][nt2][half * 2 + 0] + ff_b[col];
                float v1 = acc1[mt][nt2][half * 2 + 1] + ff_b[col + 1];
                size_t off = (size_t)row * 128 + col;
                float2 e = *(const float2*)&cx[off];
                float g0 = 1.f / (1.f + expf(-v0));
                float g1 = 1.f / (1.f + expf(-v1));
                float cy0 = g0 * (e.x + tanhf(v0));
                float cy1 = g1 * (e.y + tanhf(v1));
                *(float2*)&outp[off] = make_float2(g0 * tanhf(cy0), g1 * tanhf(cy1));
            }
        }
    }
}

// ---------------- tensor-core window attention ----------------
#define ATT_STRIDE 136    // 128 d halfs + 8 pad (272 B rows)
#define ATT_SMEM   (3 * 64 * ATT_STRIDE * 2 + 900 * 4)

__global__ void __launch_bounds__(256) attn5(
    const bf16* __restrict__ qkv, const float* __restrict__ rp,
    bf16* __restrict__ out, int shift)
{
    extern __shared__ char smr[];
    bf16* qs = (bf16*)smr;
    bf16* ks = qs + 64 * ATT_STRIDE;
    bf16* vs = ks + 64 * ATT_STRIDE;
    float* rps = (float*)(vs + 64 * ATT_STRIDE);
    int tid = threadIdx.x;
    int lane = tid & 31, warp = tid >> 5;
    int bw = blockIdx.x;
    const float SCALE = 0.17677669529663687f;

    const bf16* base = qkv + (size_t)bw * 64 * 384;
#pragma unroll
    for (int i = 0; i < 12; i++) {
        int idx = tid + i * 256;
        int n = idx / 48, part = idx % 48;
        uint4 val = *(const uint4*)(base + (size_t)n * 384 + part * 8);
        bf16* dstp = (part < 16) ? qs : (part < 32) ? ks : vs;
        *(uint4*)&dstp[n * ATT_STRIDE + (part & 15) * 8] = val;
    }
    for (int i = tid; i < 900; i += 256) rps[i] = rp[i];
    __syncthreads();

    int h = warp >> 1;
    int m0 = (warp & 1) * 32;
    int cb = h * 32;
    int lrow = lane & 15;
    int lcol = (lane >> 4) << 3;

    u32 aq[2][2][4];
#pragma unroll
    for (int mt = 0; mt < 2; mt++)
#pragma unroll
        for (int kt = 0; kt < 2; kt++)
            ldm_x4(aq[mt][kt][0], aq[mt][kt][1], aq[mt][kt][2], aq[mt][kt][3],
                   smem_u32(&qs[(m0 + 16 * mt + lrow) * ATT_STRIDE + cb + 16 * kt + lcol]));

    float sacc[2][8][4];
#pragma unroll
    for (int mt = 0; mt < 2; mt++)
#pragma unroll
        for (int nt = 0; nt < 8; nt++)
#pragma unroll
            for (int q = 0; q < 4; q++) sacc[mt][nt][q] = 0.f;

#pragma unroll
    for (int ntp = 0; ntp < 4; ntp++)
#pragma unroll
        for (int kt = 0; kt < 2; kt++) {
            u32 b0, b1, b2, b3;
            ldm_x4(b0, b1, b2, b3,
                   smem_u32(&ks[(16 * ntp + lrow) * ATT_STRIDE + cb + 16 * kt + lcol]));
#pragma unroll
            for (int mt = 0; mt < 2; mt++) {
                mma_bf(sacc[mt][2 * ntp],     aq[mt][kt], b0, b2);
                mma_bf(sacc[mt][2 * ntp + 1], aq[mt][kt], b1, b3);
            }
        }

    int widx = bw & 63;
    int wh = widx >> 3, ww = widx & 7;
#pragma unroll
    for (int mt = 0; mt < 2; mt++)
#pragma unroll
        for (int q = 0; q < 4; q++) {
            int t1 = m0 + 16 * mt + (lane >> 2) + ((q >> 1) << 3);
            int r1 = t1 >> 3, s1 = t1 & 7;
            int h1 = wh * 8 + r1, w1 = ww * 8 + s1;
            int img1 = (h1 < 56 ? 0 : (h1 < 60 ? 1 : 2)) * 3 + (w1 < 56 ? 0 : (w1 < 60 ? 1 : 2));
#pragma unroll
            for (int nt = 0; nt < 8; nt++) {
                int t2 = nt * 8 + 2 * (lane & 3) + (q & 1);
                int r2 = t2 >> 3, s2 = t2 & 7;
                float v = sacc[mt][nt][q] * SCALE
                        + rps[((r1 - r2 + 7) * 15 + (s1 - s2 + 7)) * 4 + h];
                if (shift) {
                    int h2 = wh * 8 + r2, w2 = ww * 8 + s2;
                    int img2 = (h2 < 56 ? 0 : (h2 < 60 ? 1 : 2)) * 3 + (w2 < 56 ? 0 : (w2 < 60 ? 1 : 2));
                    if (img1 != img2) v -= 100.f;
                }
                sacc[mt][nt][q] = v;
            }
        }

#pragma unroll
    for (int mt = 0; mt < 2; mt++)
#pragma unroll
        for (int half = 0; half < 2; half++) {
            float mx = -1e30f;
#pragma unroll
            for (int nt = 0; nt < 8; nt++) {
                mx = fmaxf(mx, sacc[mt][nt][2 * half]);
                mx = fmaxf(mx, sacc[mt][nt][2 * half + 1]);
            }
            mx = fmaxf(mx, __shfl_xor_sync(0xffffffffu, mx, 1));
            mx = fmaxf(mx, __shfl_xor_sync(0xffffffffu, mx, 2));
            float sum = 0.f;
#pragma unroll
            for (int nt = 0; nt < 8; nt++) {
#pragma unroll
                for (int qq = 0; qq < 2; qq++) {
                    float e = __expf(sacc[mt][nt][2 * half + qq] - mx);
                    sacc[mt][nt][2 * half + qq] = e;
                    sum += e;
                }
            }
            sum += __shfl_xor_sync(0xffffffffu, sum, 1);
            sum += __shfl_xor_sync(0xffffffffu, sum, 2);
            float inv = 1.f / sum;
#pragma unroll
            for (int nt = 0; nt < 8; nt++) {
                sacc[mt][nt][2 * half] *= inv;
                sacc[mt][nt][2 * half + 1] *= inv;
            }
        }

    u32 pa[2][4][4];
#pragma unroll
    for (int mt = 0; mt < 2; mt++)
#pragma unroll
        for (int j = 0; j < 4; j++) {
            pa[mt][j][0] = bf2(sacc[mt][2 * j][0],     sacc[mt][2 * j][1]);
            pa[mt][j][1] = bf2(sacc[mt][2 * j][2],     sacc[mt][2 * j][3]);
            pa[mt][j][2] = bf2(sacc[mt][2 * j + 1][0], sacc[mt][2 * j + 1][1]);
            pa[mt][j][3] = bf2(sacc[mt][2 * j + 1][2], sacc[mt][2 * j + 1][3]);
        }

    float oacc[2][4][4];
#pragma unroll
    for (int mt = 0; mt < 2; mt++)
#pragma unroll
        for (int nt2 = 0; nt2 < 4; nt2++)
#pragma unroll
            for (int q = 0; q < 4; q++) oacc[mt][nt2][q] = 0.f;

#pragma unroll
    for (int j = 0; j < 4; j++)
#pragma unroll
        for (int ntp = 0; ntp < 2; ntp++) {
            u32 b0, b1, b2, b3;
            ldmt_x4(b0, b1, b2, b3,
                    smem_u32(&vs[(16 * j + lrow) * ATT_STRIDE + cb + 16 * ntp + lcol]));
#pragma unroll
            for (int mt = 0; mt < 2; mt++) {
                mma_bf(oacc[mt][2 * ntp],     pa[mt][j], b0, b1);
                mma_bf(oacc[mt][2 * ntp + 1], pa[mt][j], b2, b3);
            }
        }

#pragma unroll
    for (int mt = 0; mt < 2; mt++) {
        int row0 = bw * 64 + m0 + 16 * mt + (lane >> 2);
        int col  = cb + 2 * (lane & 3);
#pragma unroll
        for (int nt2 = 0; nt2 < 4; nt2++) {
            *(u32*)&out[(size_t)row0 * 128 + col + nt2 * 8]       = bf2(oacc[mt][nt2][0], oacc[mt][nt2][1]);
            *(u32*)&out[(size_t)(row0 + 8) * 128 + col + nt2 * 8] = bf2(oacc[mt][nt2][2], oacc[mt][nt2][3]);
        }
    }
}

// ---------------- fused deformable-conv branch (offset/mask conv + gather) ----------------
__global__ void __launch_bounds__(256) local_k(
    const float* __restrict__ xt,
    const float* __restrict__ ow, const float* __restrict__ ob,
    const float* __restrict__ mw, const float* __restrict__ mb,
    bf16* __restrict__ outp)
{
    __shared__ float rows[34][128];
    __shared__ float wo_s[1152], wm_s[1152];
    __shared__ int   s_fp[3][32];
    __shared__ float s_a0[3][32], s_a1[3][32];
    __shared__ bf16  smout[32][130];
    int b  = blockIdx.x >> 7;
    int l0 = (blockIdx.x & 127) << 5;
    int tid = threadIdx.x;
    int warp = tid >> 5, lane = tid & 31;

    for (int i = tid; i < 1152; i += 256) { wo_s[i] = ow[i]; wm_s[i] = mw[i]; }
#pragma unroll
    for (int i = 0; i < 5; i++) {
        int idx = i * 256 + tid;             // float4 ids, need 34*32 = 1088
        if (idx < 1088) {
            int rr = idx >> 5, c4 = (idx & 31) << 2;
            int l = l0 - 1 + rr;
            if (l >= 0 && l < 4096)
                *(float4*)&rows[rr][c4] = *(const float4*)(xt + ((size_t)b * 4096 + l) * 128 + c4);
        }
    }
    __syncthreads();

    int c0 = lane << 2;
#pragma unroll
    for (int it = 0; it < 4; it++) {
        int tl = warp * 4 + it;              // local token 0..31
        int l = l0 + tl;
        float so[3] = {0.f, 0.f, 0.f}, sm[3] = {0.f, 0.f, 0.f};
#pragma unroll
        for (int j = 0; j < 3; j++) {
            int ll = l + j - 1;
            if (ll < 0 || ll > 4095) continue;
            float4 xv = *(const float4*)&rows[tl + j][c0];
#pragma unroll
            for (int k = 0; k < 3; k++) {
                const float* owp = wo_s + k * 384 + j;
                const float* mwp = wm_s + k * 384 + j;
                so[k] += xv.x * owp[(c0 + 0) * 3] + xv.y * owp[(c0 + 1) * 3]
                       + xv.z * owp[(c0 + 2) * 3] + xv.w * owp[(c0 + 3) * 3];
                sm[k] += xv.x * mwp[(c0 + 0) * 3] + xv.y * mwp[(c0 + 1) * 3]
                       + xv.z * mwp[(c0 + 2) * 3] + xv.w * mwp[(c0 + 3) * 3];
            }
        }
#pragma unroll
        for (int o = 16; o > 0; o >>= 1) {
#pragma unroll
            for (int k = 0; k < 3; k++) {
                so[k] += __shfl_xor_sync(0xffffffffu, so[k], o);
                sm[k] += __shfl_xor_sync(0xffffffffu, sm[k], o);
            }
        }
        if (lane < 3) {
            int k = lane;
            float off = ob[k] + so[k];
            float mk  = mb[k] + sm[k];
            float mask = 1.f / (1.f + expf(-mk));
            float pos = fminf(fmaxf((float)l + off, 0.f), 4095.f);
            float fpf = floorf(pos);
            int f = (int)fpf;
            float alpha = pos - fpf;
            s_fp[k][tl] = f;
            s_a0[k][tl] = (1.f - alpha) * mask;
            s_a1[k][tl] = alpha * mask;
        }
    }
    __syncthreads();

    // phase 2: gather + bf16, transpose via smem, coalesced (B,C,L) write
#pragma unroll
    for (int i = 0; i < 16; i++) {
        int idx = i * 256 + tid;          // 0..4095
        int dl = idx >> 7, c = idx & 127;
        float o = 0.f;
#pragma unroll
        for (int k = 0; k < 3; k++) {
            int f  = s_fp[k][dl];
            int cp = min(f + 1, 4095);
            o += xt[((size_t)b * 4096 + f)  * 128 + c] * s_a0[k][dl]
               + xt[((size_t)b * 4096 + cp) * 128 + c] * s_a1[k][dl];
        }
        smout[dl][c] = __float2bfloat16_rn(o);
    }
    __syncthreads();
#pragma unroll
    for (int i = 0; i < 16; i++) {
        int idx = i * 256 + tid;
        int c = idx >> 5, dl = idx & 31;
        outp[(size_t)b * 524288 + (size_t)c * 4096 + l0 + dl] = smout[dl][c];
    }
}

// ---------------- host launcher ----------------
extern "C" void kernel_launch(void* const* d_in, const int* in_sizes, int n_in,
                              void* d_out, int out_size)
{
    const float* xt    = (const float*)d_in[0];
    const float* hx    = (const float*)d_in[1];
    const float* cx    = (const float*)d_in[2];
    const float* red_w = (const float*)d_in[3];
    const float* red_b = (const float*)d_in[4];
    const float* n1g   = (const float*)d_in[5];
    const float* n1b   = (const float*)d_in[6];
    const float* qkvw  = (const float*)d_in[7];
    const float* qkvb  = (const float*)d_in[8];
    const float* rp    = (const float*)d_in[9];
    const float* pw    = (const float*)d_in[10];
    const float* pb    = (const float*)d_in[11];
    const float* n2g   = (const float*)d_in[12];
    const float* n2b   = (const float*)d_in[13];
    const float* f1w   = (const float*)d_in[14];
    const float* f1b   = (const float*)d_in[15];
    const float* f2w   = (const float*)d_in[16];
    const float* f2b   = (const float*)d_in[17];
    const float* off_w = (const float*)d_in[18];
    const float* off_b = (const float*)d_in[19];
    const float* msk_w = (const float*)d_in[20];
    const float* msk_b = (const float*)d_in[21];
    const float* lf_w  = (const float*)d_in[22];
    const float* lf_b  = (const float*)d_in[23];
    const float* gf_w  = (const float*)d_in[24];
    const float* gf_b  = (const float*)d_in[25];
    const float* ff_w  = (const float*)d_in[26];
    const float* ff_b  = (const float*)d_in[27];

    float* px;
    bf16 *pbig16, *pxw16, *patt16, *ploc16, *px16;
    bf16 *predT, *pqkvT, *ppwT, *pf1T, *pf2T, *plfT, *pgfT, *pffT;
    cudaGetSymbolAddress((void**)&px,    d_x);
    cudaGetSymbolAddress((void**)&pbig16, g_big16);
    cudaGetSymbolAddress((void**)&pxw16, g_xw16);
    cudaGetSymbolAddress((void**)&patt16, g_att16);
    cudaGetSymbolAddress((void**)&ploc16, g_loc16);
    cudaGetSymbolAddress((void**)&px16,  g_x16);
    cudaGetSymbolAddress((void**)&predT, g_redT);
    cudaGetSymbolAddress((void**)&pqkvT, g_qkvT);
    cudaGetSymbolAddress((void**)&ppwT,  g_pwT);
    cudaGetSymbolAddress((void**)&pf1T,  g_f1T);
    cudaGetSymbolAddress((void**)&pf2T,  g_f2T);
    cudaGetSymbolAddress((void**)&plfT,  g_lfT);
    cudaGetSymbolAddress((void**)&pgfT,  g_gfT);
    cudaGetSymbolAddress((void**)&pffT,  g_ffT);

    cudaFuncSetAttribute(gemm_tc<M_CONCAT_LN,128,256>,  cudaFuncAttributeMaxDynamicSharedMemorySize, GEMM_SMEM);
    cudaFuncSetAttribute(gemm_tc<M_PLAIN,384,128>,      cudaFuncAttributeMaxDynamicSharedMemorySize, GEMM_SMEM);
    cudaFuncSetAttribute(gemm_tc<M_PERMRES_LN,128,128>, cudaFuncAttributeMaxDynamicSharedMemorySize, GEMM_SMEM);
    cudaFuncSetAttribute(gemm_tc<M_GELU,512,128>,       cudaFuncAttributeMaxDynamicSharedMemorySize, GEMM_SMEM);
    cudaFuncSetAttribute(gemm_tc<M_RES_LN,128,512>,     cudaFuncAttributeMaxDynamicSharedMemorySize, GEMM_SMEM);
    cudaFuncSetAttribute(gemm_tc<M_RES,128,512>,        cudaFuncAttributeMaxDynamicSharedMemorySize, GEMM_SMEM);
    cudaFuncSetAttribute(fusion_k,                      cudaFuncAttributeMaxDynamicSharedMemorySize, GEMM_SMEM);
    cudaFuncSetAttribute(attn5,                         cudaFuncAttributeMaxDynamicSharedMemorySize, ATT_SMEM);

    // weight transpose-convert (fp32 KxN -> bf16 NxK)
    WPack wp;
    wp.e[0]  = { red_w,           predT,           256, 128 };
    wp.e[1]  = { qkvw,            pqkvT,           128, 384 };
    wp.e[2]  = { qkvw + 49152,    pqkvT + 49152,   128, 384 };
    wp.e[3]  = { pw,              ppwT,            128, 128 };
    wp.e[4]  = { pw + 16384,      ppwT + 16384,    128, 128 };
    wp.e[5]  = { f1w,             pf1T,            128, 512 };
    wp.e[6]  = { f1w + 65536,     pf1T + 65536,    128, 512 };
    wp.e[7]  = { f2w,             pf2T,            512, 128 };
    wp.e[8]  = { f2w + 65536,     pf2T + 65536,    512, 128 };
    wp.e[9]  = { lf_w,            plfT,            128, 128 };
    wp.e[10] = { gf_w,            pgfT,            128, 128 };
    wp.e[11] = { ff_w,            pffT,            128, 128 };
    wconv_k<<<dim3(48, 12), 256>>>(wp);

    // local (deformable) branch — fused offsets + gather
    local_k<<<Bn * 128, 256>>>(xt, off_w, off_b, msk_w, msk_b, ploc16);

    // global branch: reduce GEMM with fused concat input + fused LN1(block0, shift 0)
    gemm_tc<M_CONCAT_LN,128,256><<<dim3(1, 256), 512, GEMM_SMEM>>>(
        nullptr, predT, red_b, nullptr, px, pxw16, n1g, n1b, 0, xt, hx);

    for (int i = 0; i < 2; i++) {
        int shift = i ? 4 : 0;
        gemm_tc<M_PLAIN,384,128><<<dim3(3, 256), 512, GEMM_SMEM>>>(
            pxw16, pqkvT + i * 49152, qkvb + i * 384, nullptr,
            nullptr, pbig16, nullptr, nullptr, 0, nullptr, nullptr);
        attn5<<<512, 256, ATT_SMEM>>>(pbig16, rp + i * 900, patt16, shift);
        gemm_tc<M_PERMRES_LN,128,128><<<dim3(1, 256), 512, GEMM_SMEM>>>(
            patt16, ppwT + i * 16384, pb + i * 128, px,
            px, pxw16, n2g + i * 128, n2b + i * 128, shift, nullptr, nullptr);
        gemm_tc<M_GELU,512,128><<<dim3(4, 256), 512, GEMM_SMEM>>>(
            pxw16, pf1T + i * 65536, f1b + i * 512, nullptr,
            nullptr, pbig16, nullptr, nullptr, 0, nullptr, nullptr);
        if (i == 0) {
            gemm_tc<M_RES_LN,128,512><<<dim3(1, 256), 512, GEMM_SMEM>>>(
                pbig16, pf2T, f2b, px,
                px, pxw16, n1g + 128, n1b + 128, 4, nullptr, nullptr);
        } else {
            gemm_tc<M_RES,128,512><<<dim3(1, 256), 512, GEMM_SMEM>>>(
                pbig16, pf2T + 65536, f2b + 128, px,
                px, px16, nullptr, nullptr, 0, nullptr, nullptr);
        }
    }

    // fused fusion + LSTM gate
    fusion_k<<<256, 512, GEMM_SMEM>>>(px16, ploc16, pgfT, plfT, pffT,
                                      gf_b, lf_b, ff_b, cx, (float*)d_out);
}